// round 1
// baseline (speedup 1.0000x reference)
#include <cuda_runtime.h>
#include <cuda_bf16.h>
#include <math.h>

// Problem constants
#define BS    32
#define NMM   256
#define NV    196
#define NA    60
#define NKV   256
#define DIM   768
#define HEADS 12
#define HD    64
#define KVDIM 1536

#define OUT_ELEMS  (BS * NMM * DIM)                 // 6,291,456
#define ATTN_ELEMS (BS * HEADS * NMM * NKV)         // 25,165,824

// Scratch (device globals; no allocations allowed)
__device__ float g_Q[BS * NMM * DIM];       // [b*256+q][h*64+d]
__device__ float g_KV[BS * NKV * KVDIM];    // [b*256+k][ (0:K|768:V) + h*64+d ]
__device__ float g_O[BS * NMM * DIM];       // [b*256+q][h*64+d]
__device__ float g_attn_fallback[ATTN_ELEMS];

// ---------------------------------------------------------------------------
// Generic fp32 SGEMM: C[M,N] = A[M,K] @ B[K,N] (+bias). BM=BN=128, BK=16,
// 256 threads, 8x8 register micro-tile. GATHER mode builds A rows from the
// concat(xv, xa) layout.
// ---------------------------------------------------------------------------
#define BM 128
#define BN 128
#define BK 16
#define TM 8
#define TN 8

template <bool GATHER, bool BIAS>
__global__ __launch_bounds__(256)
void sgemm_kernel(const float* __restrict__ A, const float* __restrict__ A2,
                  const float* __restrict__ B, const float* __restrict__ bias,
                  float* __restrict__ C, int M, int N, int K) {
    __shared__ float As[BK][BM];
    __shared__ float Bs[BK][BN];

    const int tid = threadIdx.x;
    const int br  = blockIdx.y * BM;
    const int bc  = blockIdx.x * BN;
    const int tr  = (tid / 16) * TM;
    const int tc  = (tid % 16) * TN;

    float acc[TM][TN];
    #pragma unroll
    for (int m = 0; m < TM; m++)
        #pragma unroll
        for (int n = 0; n < TN; n++) acc[m][n] = 0.0f;

    for (int k0 = 0; k0 < K; k0 += BK) {
        // Load A tile: 128x16 = 512 float4, transposed into As[k][m]
        #pragma unroll
        for (int i = 0; i < 2; i++) {
            int f    = tid + i * 256;      // 0..511
            int arow = f >> 2;             // 0..127
            int acol = (f & 3) * 4;        // 0,4,8,12
            int grow = br + arow;
            const float* aptr;
            if (GATHER) {
                int b = grow >> 8;
                int r = grow & 255;
                aptr = (r < NV) ? (A  + ((size_t)(b * NV + r)) * DIM)
                                : (A2 + ((size_t)(b * NA + (r - NV))) * DIM);
            } else {
                aptr = A + (size_t)grow * K;
            }
            float4 v = *reinterpret_cast<const float4*>(aptr + k0 + acol);
            As[acol + 0][arow] = v.x;
            As[acol + 1][arow] = v.y;
            As[acol + 2][arow] = v.z;
            As[acol + 3][arow] = v.w;
        }
        // Load B tile: 16x128 = 512 float4 (row-major, direct)
        #pragma unroll
        for (int i = 0; i < 2; i++) {
            int f    = tid + i * 256;
            int brow = f >> 5;             // 0..15
            int bcol = (f & 31) * 4;       // 0..124
            float4 v = *reinterpret_cast<const float4*>(B + (size_t)(k0 + brow) * N + bc + bcol);
            *reinterpret_cast<float4*>(&Bs[brow][bcol]) = v;
        }
        __syncthreads();

        #pragma unroll
        for (int kk = 0; kk < BK; kk++) {
            float ra[TM], rb[TN];
            #pragma unroll
            for (int m = 0; m < TM; m++) ra[m] = As[kk][tr + m];
            #pragma unroll
            for (int n = 0; n < TN; n++) rb[n] = Bs[kk][tc + n];
            #pragma unroll
            for (int m = 0; m < TM; m++)
                #pragma unroll
                for (int n = 0; n < TN; n++) acc[m][n] += ra[m] * rb[n];
        }
        __syncthreads();
    }

    // Writeback (vectorized), optional bias
    #pragma unroll
    for (int m = 0; m < TM; m++) {
        float* crow = C + (size_t)(br + tr + m) * N + bc + tc;
        #pragma unroll
        for (int n = 0; n < TN; n += 4) {
            float4 v;
            v.x = acc[m][n + 0];
            v.y = acc[m][n + 1];
            v.z = acc[m][n + 2];
            v.w = acc[m][n + 3];
            if (BIAS) {
                v.x += bias[bc + tc + n + 0];
                v.y += bias[bc + tc + n + 1];
                v.z += bias[bc + tc + n + 2];
                v.w += bias[bc + tc + n + 3];
            }
            *reinterpret_cast<float4*>(crow + n) = v;
        }
    }
}

// ---------------------------------------------------------------------------
// Fused scores + softmax kernel.
// Block: 256 threads (8 warps), handles 64 q rows of one (b,h).
// K tile held transposed in smem as Kst[d][k] with row stride 257 (pad for
// conflict-free loads). Each warp processes 8 rows with 8x8 register tiles.
// ---------------------------------------------------------------------------
#define KST_STRIDE 257
#define ATT_SMEM_FLOATS (64 * KST_STRIDE + 64 * 64)

__global__ __launch_bounds__(256)
void attn_softmax_kernel(const float* __restrict__ Q, const float* __restrict__ KV,
                         float* __restrict__ attn) {
    extern __shared__ float sm[];
    float* Kst = sm;                      // [64][257] : Kst[d][k]
    float* Qs  = sm + 64 * KST_STRIDE;    // [64][64]  : Qs[r][d]

    const int bh = blockIdx.y;
    const int b  = bh / HEADS;
    const int h  = bh % HEADS;
    const int q0 = blockIdx.x * 64;
    const int tid  = threadIdx.x;
    const int lane = tid & 31;
    const int w    = tid >> 5;

    // Load K transposed: gmem coalesced along d, smem stride-257 stores
    for (int idx = tid; idx < 64 * NKV; idx += 256) {
        int k = idx >> 6;
        int d = idx & 63;
        Kst[d * KST_STRIDE + k] = KV[(size_t)(b * NKV + k) * KVDIM + h * HD + d];
    }
    // Load Q rows
    for (int idx = tid; idx < 64 * 64; idx += 256) {
        int r = idx >> 6;
        int d = idx & 63;
        Qs[r * 64 + d] = Q[(size_t)(b * NMM + q0 + r) * DIM + h * HD + d];
    }
    __syncthreads();

    const int r0 = w * 8;
    float acc[8][8];
    #pragma unroll
    for (int rr = 0; rr < 8; rr++)
        #pragma unroll
        for (int j = 0; j < 8; j++) acc[rr][j] = 0.0f;

    #pragma unroll 8
    for (int d = 0; d < HD; d++) {
        float qv[8];
        #pragma unroll
        for (int rr = 0; rr < 8; rr++) qv[rr] = Qs[(r0 + rr) * 64 + d];
        #pragma unroll
        for (int j = 0; j < 8; j++) {
            float kv = Kst[d * KST_STRIDE + lane + 32 * j];
            #pragma unroll
            for (int rr = 0; rr < 8; rr++) acc[rr][j] += qv[rr] * kv;
        }
    }

    const float scale = 0.125f;  // 64^-0.5
    float* out = attn + ((size_t)bh * NMM + q0 + r0) * NKV;

    #pragma unroll
    for (int rr = 0; rr < 8; rr++) {
        float s[8];
        float m = -INFINITY;
        #pragma unroll
        for (int j = 0; j < 8; j++) {
            s[j] = acc[rr][j] * scale;
            m = fmaxf(m, s[j]);
        }
        #pragma unroll
        for (int o = 16; o > 0; o >>= 1) m = fmaxf(m, __shfl_xor_sync(0xffffffffu, m, o));
        float sum = 0.0f;
        #pragma unroll
        for (int j = 0; j < 8; j++) {
            s[j] = expf(s[j] - m);
            sum += s[j];
        }
        #pragma unroll
        for (int o = 16; o > 0; o >>= 1) sum += __shfl_xor_sync(0xffffffffu, sum, o);
        float inv = 1.0f / sum;
        #pragma unroll
        for (int j = 0; j < 8; j++) out[rr * NKV + lane + 32 * j] = s[j] * inv;
    }
}

// ---------------------------------------------------------------------------
// Batched AV GEMM: per (b,h): O[256,64] = attn[256,256] @ V[256,64]
// Block: 256 threads, tile 64x64, BK=32, 4x4 micro-tile.
// ---------------------------------------------------------------------------
__global__ __launch_bounds__(256)
void av_gemm_kernel(const float* __restrict__ attn, const float* __restrict__ KV,
                    float* __restrict__ O) {
    __shared__ float As2[32][64];   // transposed attn tile: As2[k][m]
    __shared__ float Bs2[32][64];   // V tile: Bs2[k][n]

    const int bh = blockIdx.y;
    const int b  = bh / HEADS;
    const int h  = bh % HEADS;
    const int m0 = blockIdx.x * 64;
    const int tid = threadIdx.x;
    const int tr  = (tid / 16) * 4;
    const int tc  = (tid % 16) * 4;

    const float* Abase = attn + (size_t)bh * NMM * NKV;

    float acc[4][4];
    #pragma unroll
    for (int m = 0; m < 4; m++)
        #pragma unroll
        for (int n = 0; n < 4; n++) acc[m][n] = 0.0f;

    for (int k0 = 0; k0 < NKV; k0 += 32) {
        #pragma unroll
        for (int i = 0; i < 2; i++) {
            int f  = tid + i * 256;     // 0..511
            int ar = f >> 3;            // 0..63
            int ac = (f & 7) * 4;       // 0..28
            float4 v = *reinterpret_cast<const float4*>(Abase + (size_t)(m0 + ar) * NKV + k0 + ac);
            As2[ac + 0][ar] = v.x;
            As2[ac + 1][ar] = v.y;
            As2[ac + 2][ar] = v.z;
            As2[ac + 3][ar] = v.w;
        }
        #pragma unroll
        for (int i = 0; i < 2; i++) {
            int f   = tid + i * 256;
            int brr = f >> 4;           // 0..31
            int bcc = (f & 15) * 4;     // 0..60
            float4 v = *reinterpret_cast<const float4*>(
                KV + (size_t)(b * NKV + k0 + brr) * KVDIM + DIM + h * HD + bcc);
            *reinterpret_cast<float4*>(&Bs2[brr][bcc]) = v;
        }
        __syncthreads();

        #pragma unroll
        for (int kk = 0; kk < 32; kk++) {
            float ra[4], rb[4];
            #pragma unroll
            for (int m = 0; m < 4; m++) ra[m] = As2[kk][tr + m];
            #pragma unroll
            for (int n = 0; n < 4; n++) rb[n] = Bs2[kk][tc + n];
            #pragma unroll
            for (int m = 0; m < 4; m++)
                #pragma unroll
                for (int n = 0; n < 4; n++) acc[m][n] += ra[m] * rb[n];
        }
        __syncthreads();
    }

    #pragma unroll
    for (int m = 0; m < 4; m++) {
        float4 v;
        v.x = acc[m][0]; v.y = acc[m][1]; v.z = acc[m][2]; v.w = acc[m][3];
        *reinterpret_cast<float4*>(&O[(size_t)(b * NMM + m0 + tr + m) * DIM + h * HD + tc]) = v;
    }
}

// ---------------------------------------------------------------------------
// Launch
// ---------------------------------------------------------------------------
extern "C" void kernel_launch(void* const* d_in, const int* in_sizes, int n_in,
                              void* d_out, int out_size) {
    const float* xmm   = (const float*)d_in[0];
    const float* xv    = (const float*)d_in[1];
    const float* xa    = (const float*)d_in[2];
    const float* Wq    = (const float*)d_in[3];
    const float* Wkv   = (const float*)d_in[4];
    const float* Wproj = (const float*)d_in[5];
    const float* bproj = (const float*)d_in[6];
    float* out = (float*)d_out;

    float *Qb, *KVb, *Ob, *attn_fb;
    cudaGetSymbolAddress((void**)&Qb,  g_Q);
    cudaGetSymbolAddress((void**)&KVb, g_KV);
    cudaGetSymbolAddress((void**)&Ob,  g_O);
    cudaGetSymbolAddress((void**)&attn_fb, g_attn_fallback);

    // attn destination: second part of d_out if it fits, else scratch
    float* attn = (out_size >= (OUT_ELEMS + ATTN_ELEMS)) ? (out + OUT_ELEMS) : attn_fb;

    const int M = BS * NMM;  // 8192

    // 1) Q = xmm @ Wq
    {
        dim3 grid(DIM / BN, M / BM);
        sgemm_kernel<false, false><<<grid, 256>>>(xmm, nullptr, Wq, nullptr, Qb, M, DIM, DIM);
    }
    // 2) KV = concat(xv, xa) @ Wkv  (gathered A)
    {
        dim3 grid(KVDIM / BN, M / BM);
        sgemm_kernel<true, false><<<grid, 256>>>(xv, xa, Wkv, nullptr, KVb, M, KVDIM, DIM);
    }
    // 3) scores + softmax -> attn
    {
        static const size_t smem = ATT_SMEM_FLOATS * sizeof(float);
        cudaFuncSetAttribute(attn_softmax_kernel,
                             cudaFuncAttributeMaxDynamicSharedMemorySize, (int)smem);
        dim3 grid(NMM / 64, BS * HEADS);
        attn_softmax_kernel<<<grid, 256, smem>>>(Qb, KVb, attn);
    }
    // 4) O = attn @ V (batched per b,h)
    {
        dim3 grid(NMM / 64, BS * HEADS);
        av_gemm_kernel<<<grid, 256>>>(attn, KVb, Ob);
    }
    // 5) out = O @ Wproj + bproj
    {
        dim3 grid(DIM / BN, M / BM);
        sgemm_kernel<false, true><<<grid, 256>>>(Ob, nullptr, Wproj, bproj, out, M, DIM, DIM);
    }
}

// round 3
// speedup vs baseline: 1.0811x; 1.0811x over previous
#include <cuda_runtime.h>
#include <cuda_bf16.h>
#include <math.h>
#include <stdint.h>

// Problem constants
#define BS    32
#define NMM   256
#define NV    196
#define NA    60
#define NKV   256
#define DIM   768
#define HEADS 12
#define HD    64
#define KVDIM 1536

#define OUT_ELEMS  (BS * NMM * DIM)                 // 6,291,456
#define ATTN_ELEMS (BS * HEADS * NMM * NKV)         // 25,165,824
#define M_ROWS     (BS * NMM)                       // 8192

// ---------------------------------------------------------------------------
// Scratch (device globals; no allocations allowed)
// ---------------------------------------------------------------------------
__device__ float g_Q[M_ROWS * DIM];
__device__ float g_KV[M_ROWS * KVDIM];
__device__ float g_O[M_ROWS * DIM];
__device__ float g_attn_fallback[ATTN_ELEMS];

__device__ __nv_bfloat16 g_xmm_h[M_ROWS * DIM];
__device__ __nv_bfloat16 g_xmm_l[M_ROWS * DIM];
__device__ __nv_bfloat16 g_xsrc_h[M_ROWS * DIM];
__device__ __nv_bfloat16 g_xsrc_l[M_ROWS * DIM];
__device__ __nv_bfloat16 g_O_h[M_ROWS * DIM];
__device__ __nv_bfloat16 g_O_l[M_ROWS * DIM];
__device__ __nv_bfloat16 g_WqT_h[DIM * DIM];
__device__ __nv_bfloat16 g_WqT_l[DIM * DIM];
__device__ __nv_bfloat16 g_WkvT_h[KVDIM * DIM];
__device__ __nv_bfloat16 g_WkvT_l[KVDIM * DIM];
__device__ __nv_bfloat16 g_WpT_h[DIM * DIM];
__device__ __nv_bfloat16 g_WpT_l[DIM * DIM];

// ---------------------------------------------------------------------------
// PTX helpers (sm_80-era: cp.async, ldmatrix, mma.sync — assemble on sm_103 base)
// ---------------------------------------------------------------------------
__device__ __forceinline__ uint32_t smem_u32(const void* p) {
    uint32_t a;
    asm("{ .reg .u64 t; cvta.to.shared.u64 t, %1; cvt.u32.u64 %0, t; }" : "=r"(a) : "l"(p));
    return a;
}

__device__ __forceinline__ void cp_async16(uint32_t sa, const void* gp) {
    asm volatile("cp.async.cg.shared.global [%0], [%1], 16;" :: "r"(sa), "l"(gp) : "memory");
}
__device__ __forceinline__ void cp_commit() {
    asm volatile("cp.async.commit_group;" ::: "memory");
}
template <int N>
__device__ __forceinline__ void cp_wait() {
    asm volatile("cp.async.wait_group %0;" :: "n"(N) : "memory");
}

__device__ __forceinline__ void ldsm4(uint32_t& r0, uint32_t& r1, uint32_t& r2, uint32_t& r3,
                                      uint32_t addr) {
    asm volatile("ldmatrix.sync.aligned.m8n8.x4.shared.b16 {%0,%1,%2,%3}, [%4];"
                 : "=r"(r0), "=r"(r1), "=r"(r2), "=r"(r3) : "r"(addr));
}

__device__ __forceinline__ void mma16816(float* c, const uint32_t* a, uint32_t b0, uint32_t b1) {
    asm volatile(
        "mma.sync.aligned.m16n8k16.row.col.f32.bf16.bf16.f32 "
        "{%0,%1,%2,%3}, {%4,%5,%6,%7}, {%8,%9}, {%0,%1,%2,%3};"
        : "+f"(c[0]), "+f"(c[1]), "+f"(c[2]), "+f"(c[3])
        : "r"(a[0]), "r"(a[1]), "r"(a[2]), "r"(a[3]), "r"(b0), "r"(b1));
}

// ---------------------------------------------------------------------------
// Conversion kernels: fp32 -> (bf16 hi, bf16 lo)
// ---------------------------------------------------------------------------
__device__ __forceinline__ void split4(float4 v, uint2& hv, uint2& lv) {
    __nv_bfloat16 h0 = __float2bfloat16(v.x);
    __nv_bfloat16 h1 = __float2bfloat16(v.y);
    __nv_bfloat16 h2 = __float2bfloat16(v.z);
    __nv_bfloat16 h3 = __float2bfloat16(v.w);
    __nv_bfloat16 l0 = __float2bfloat16(v.x - __bfloat162float(h0));
    __nv_bfloat16 l1 = __float2bfloat16(v.y - __bfloat162float(h1));
    __nv_bfloat16 l2 = __float2bfloat16(v.z - __bfloat162float(h2));
    __nv_bfloat16 l3 = __float2bfloat16(v.w - __bfloat162float(h3));
    __nv_bfloat162 ph0 = __halves2bfloat162(h0, h1);
    __nv_bfloat162 ph1 = __halves2bfloat162(h2, h3);
    __nv_bfloat162 pl0 = __halves2bfloat162(l0, l1);
    __nv_bfloat162 pl1 = __halves2bfloat162(l2, l3);
    hv.x = *reinterpret_cast<uint32_t*>(&ph0);
    hv.y = *reinterpret_cast<uint32_t*>(&ph1);
    lv.x = *reinterpret_cast<uint32_t*>(&pl0);
    lv.y = *reinterpret_cast<uint32_t*>(&pl1);
}

__global__ __launch_bounds__(256)
void split_kernel(const float4* __restrict__ in, uint2* __restrict__ h,
                  uint2* __restrict__ l, int n4) {
    int i = blockIdx.x * 256 + threadIdx.x;
    if (i < n4) {
        uint2 hv, lv;
        split4(in[i], hv, lv);
        h[i] = hv;
        l[i] = lv;
    }
}

// Build concat(xv, xa) rows, split into hi/lo
__global__ __launch_bounds__(256)
void gather_split_kernel(const float* __restrict__ xv, const float* __restrict__ xa,
                         uint2* __restrict__ h, uint2* __restrict__ l) {
    int i = blockIdx.x * 256 + threadIdx.x;         // over M_ROWS * (DIM/4)
    const int C4 = DIM / 4;                         // 192
    int row = i / C4;
    int c4  = i - row * C4;
    int b = row >> 8;
    int r = row & 255;
    const float4* src = (r < NV)
        ? reinterpret_cast<const float4*>(xv + (size_t)(b * NV + r) * DIM)
        : reinterpret_cast<const float4*>(xa + (size_t)(b * NA + (r - NV)) * DIM);
    uint2 hv, lv;
    split4(src[c4], hv, lv);
    h[i] = hv;
    l[i] = lv;
}

// W[K][N] -> WT[N][K] split into hi/lo (tiled transpose)
__global__ __launch_bounds__(256)
void transpose_split_kernel(const float* __restrict__ W, __nv_bfloat16* __restrict__ Th,
                            __nv_bfloat16* __restrict__ Tl, int K, int N) {
    __shared__ float t[32][33];
    int k0 = blockIdx.y * 32, n0 = blockIdx.x * 32;
    int x = threadIdx.x, y = threadIdx.y;  // 32 x 8
    #pragma unroll
    for (int i = 0; i < 32; i += 8)
        t[y + i][x] = W[(size_t)(k0 + y + i) * N + n0 + x];
    __syncthreads();
    #pragma unroll
    for (int i = 0; i < 32; i += 8) {
        float v = t[x][y + i];
        __nv_bfloat16 hi = __float2bfloat16(v);
        __nv_bfloat16 lo = __float2bfloat16(v - __bfloat162float(hi));
        size_t o = (size_t)(n0 + y + i) * K + k0 + x;
        Th[o] = hi;
        Tl[o] = lo;
    }
}

// ---------------------------------------------------------------------------
// Split-bf16 mma.sync GEMM: C[M,N] = A[M,K] @ B[K,N] in ~fp32 precision.
// A given as (Ah, Al) row-major [M][K]; B given as (BhT, BlT) = B^T [N][K].
// Tile 128x128, BK=32, cp.async 2-stage pipeline, 8 warps (2x4), each 64x32.
// Terms: Ah*Bh + Al*Bh + Ah*Bl (fp32 accum).
// ---------------------------------------------------------------------------
#define GK 768                 // K is always 768
#define PAD_ROW 80             // bytes per smem row (32 bf16 + 8 pad)
#define ARR_BYTES (128 * PAD_ROW)     // 10240
#define STAGE_BYTES (4 * ARR_BYTES)   // 40960
#define GEMM_SMEM (2 * STAGE_BYTES)   // 81920

__global__ __launch_bounds__(256, 1)
void mma_gemm_kernel(const __nv_bfloat16* __restrict__ Ah, const __nv_bfloat16* __restrict__ Al,
                     const __nv_bfloat16* __restrict__ BhT, const __nv_bfloat16* __restrict__ BlT,
                     const float* __restrict__ bias, float* __restrict__ C,
                     int N, int hasBias) {
    extern __shared__ char smem[];
    const uint32_t sb = smem_u32(smem);

    const int tid  = threadIdx.x;
    const int lane = tid & 31;
    const int wid  = tid >> 5;
    const int wr   = wid >> 2;   // 0..1 -> m offset wr*64
    const int wc   = wid & 3;    // 0..3 -> n offset wc*32
    const int m0   = blockIdx.y * 128;
    const int n0   = blockIdx.x * 128;

    const __nv_bfloat16* base0 = Ah  + (size_t)m0 * GK;
    const __nv_bfloat16* base1 = Al  + (size_t)m0 * GK;
    const __nv_bfloat16* base2 = BhT + (size_t)n0 * GK;
    const __nv_bfloat16* base3 = BlT + (size_t)n0 * GK;

    // per-thread load slots: 8 x cp.async(16B) per stage
    auto issue_stage = [&](int chunk, int s) {
        const int k0 = chunk << 5;
        const uint32_t sbase = sb + s * STAGE_BYTES;
        #pragma unroll
        for (int it = 0; it < 8; it++) {
            const int arr = it >> 1;
            const int j   = tid + (it & 1) * 256;     // 0..511
            const int row = j >> 2;
            const int q   = j & 3;
            const __nv_bfloat16* gp =
                (arr == 0 ? base0 : arr == 1 ? base1 : arr == 2 ? base2 : base3)
                + (size_t)row * GK + k0 + q * 8;
            cp_async16(sbase + arr * ARR_BYTES + row * PAD_ROW + q * 16, gp);
        }
        cp_commit();
    };

    float c[4][4][4];
    #pragma unroll
    for (int i = 0; i < 4; i++)
        #pragma unroll
        for (int j = 0; j < 4; j++)
            #pragma unroll
            for (int k = 0; k < 4; k++) c[i][j][k] = 0.0f;

    const int r8  = lane & 7;
    const int sub = lane >> 3;
    const int lrow = r8 + ((sub & 1) << 3);   // 0..15 row within 16-row tile
    const int lcol = (sub >> 1) << 3;         // 0 or 8 col offset

    issue_stage(0, 0);

    const int nchunks = GK / 32;  // 24
    for (int i = 0; i < nchunks; i++) {
        const int s = i & 1;
        if (i + 1 < nchunks) {
            issue_stage(i + 1, 1 - s);
            cp_wait<1>();
        } else {
            cp_wait<0>();
        }
        __syncthreads();

        const uint32_t st = sb + s * STAGE_BYTES;
        const uint32_t aH_base = st + 0 * ARR_BYTES + (wr * 64 + lrow) * PAD_ROW + lcol * 2;
        const uint32_t aL_base = st + 1 * ARR_BYTES + (wr * 64 + lrow) * PAD_ROW + lcol * 2;
        const uint32_t bH_base = st + 2 * ARR_BYTES + (wc * 32 + lrow) * PAD_ROW + lcol * 2;
        const uint32_t bL_base = st + 3 * ARR_BYTES + (wc * 32 + lrow) * PAD_ROW + lcol * 2;

        #pragma unroll
        for (int kk = 0; kk < 2; kk++) {
            const uint32_t ko = kk * 32;  // 16 elems * 2B

            // B frags: 2 x ldsm4 per array cover 4 n8-tiles
            uint32_t bh[4][2], bl[4][2];
            #pragma unroll
            for (int bt = 0; bt < 2; bt++) {
                uint32_t r0, r1, r2, r3;
                ldsm4(r0, r1, r2, r3, bH_base + bt * 16 * PAD_ROW + ko);
                bh[bt * 2 + 0][0] = r0; bh[bt * 2 + 0][1] = r2;
                bh[bt * 2 + 1][0] = r1; bh[bt * 2 + 1][1] = r3;
                ldsm4(r0, r1, r2, r3, bL_base + bt * 16 * PAD_ROW + ko);
                bl[bt * 2 + 0][0] = r0; bl[bt * 2 + 0][1] = r2;
                bl[bt * 2 + 1][0] = r1; bl[bt * 2 + 1][1] = r3;
            }

            #pragma unroll
            for (int mt = 0; mt < 4; mt++) {
                uint32_t aH[4], aL[4];
                ldsm4(aH[0], aH[1], aH[2], aH[3], aH_base + mt * 16 * PAD_ROW + ko);
                ldsm4(aL[0], aL[1], aL[2], aL[3], aL_base + mt * 16 * PAD_ROW + ko);
                #pragma unroll
                for (int ni = 0; ni < 4; ni++)
                    mma16816(c[mt][ni], aH, bh[ni][0], bh[ni][1]);
                #pragma unroll
                for (int ni = 0; ni < 4; ni++)
                    mma16816(c[mt][ni], aL, bh[ni][0], bh[ni][1]);
                #pragma unroll
                for (int ni = 0; ni < 4; ni++)
                    mma16816(c[mt][ni], aH, bl[ni][0], bl[ni][1]);
            }
        }
        __syncthreads();
    }

    // Epilogue: write C rows (+bias)
    const int crow0 = m0 + wr * 64 + (lane >> 2);
    const int ccol0 = n0 + wc * 32 + (lane & 3) * 2;
    #pragma unroll
    for (int mt = 0; mt < 4; mt++) {
        #pragma unroll
        for (int ni = 0; ni < 4; ni++) {
            const int cc = ccol0 + ni * 8;
            float b0 = 0.f, b1 = 0.f;
            if (hasBias) { b0 = bias[cc]; b1 = bias[cc + 1]; }
            float2 v0 = { c[mt][ni][0] + b0, c[mt][ni][1] + b1 };
            float2 v1 = { c[mt][ni][2] + b0, c[mt][ni][3] + b1 };
            *reinterpret_cast<float2*>(C + (size_t)(crow0 + mt * 16)     * N + cc) = v0;
            *reinterpret_cast<float2*>(C + (size_t)(crow0 + mt * 16 + 8) * N + cc) = v1;
        }
    }
}

// ---------------------------------------------------------------------------
// Fused scores + softmax kernel (fp32)
// ---------------------------------------------------------------------------
#define KST_STRIDE 257
#define ATT_SMEM_FLOATS (64 * KST_STRIDE + 64 * 64)

__global__ __launch_bounds__(256)
void attn_softmax_kernel(const float* __restrict__ Q, const float* __restrict__ KV,
                         float* __restrict__ attn) {
    extern __shared__ float sm[];
    float* Kst = sm;
    float* Qs  = sm + 64 * KST_STRIDE;

    const int bh = blockIdx.y;
    const int b  = bh / HEADS;
    const int h  = bh % HEADS;
    const int q0 = blockIdx.x * 64;
    const int tid  = threadIdx.x;
    const int lane = tid & 31;
    const int w    = tid >> 5;

    for (int idx = tid; idx < 64 * NKV; idx += 256) {
        int k = idx >> 6;
        int d = idx & 63;
        Kst[d * KST_STRIDE + k] = KV[(size_t)(b * NKV + k) * KVDIM + h * HD + d];
    }
    for (int idx = tid; idx < 64 * 64; idx += 256) {
        int r = idx >> 6;
        int d = idx & 63;
        Qs[r * 64 + d] = Q[(size_t)(b * NMM + q0 + r) * DIM + h * HD + d];
    }
    __syncthreads();

    const int r0 = w * 8;
    float acc[8][8];
    #pragma unroll
    for (int rr = 0; rr < 8; rr++)
        #pragma unroll
        for (int j = 0; j < 8; j++) acc[rr][j] = 0.0f;

    #pragma unroll 8
    for (int d = 0; d < HD; d++) {
        float qv[8];
        #pragma unroll
        for (int rr = 0; rr < 8; rr++) qv[rr] = Qs[(r0 + rr) * 64 + d];
        #pragma unroll
        for (int j = 0; j < 8; j++) {
            float kv = Kst[d * KST_STRIDE + lane + 32 * j];
            #pragma unroll
            for (int rr = 0; rr < 8; rr++) acc[rr][j] += qv[rr] * kv;
        }
    }

    const float scale = 0.125f;
    float* out = attn + ((size_t)bh * NMM + q0 + r0) * NKV;

    #pragma unroll
    for (int rr = 0; rr < 8; rr++) {
        float s[8];
        float m = -INFINITY;
        #pragma unroll
        for (int j = 0; j < 8; j++) {
            s[j] = acc[rr][j] * scale;
            m = fmaxf(m, s[j]);
        }
        #pragma unroll
        for (int o = 16; o > 0; o >>= 1) m = fmaxf(m, __shfl_xor_sync(0xffffffffu, m, o));
        float sum = 0.0f;
        #pragma unroll
        for (int j = 0; j < 8; j++) {
            s[j] = expf(s[j] - m);
            sum += s[j];
        }
        #pragma unroll
        for (int o = 16; o > 0; o >>= 1) sum += __shfl_xor_sync(0xffffffffu, sum, o);
        float inv = 1.0f / sum;
        #pragma unroll
        for (int j = 0; j < 8; j++) out[rr * NKV + lane + 32 * j] = s[j] * inv;
    }
}

// ---------------------------------------------------------------------------
// Batched AV GEMM (fp32)
// ---------------------------------------------------------------------------
__global__ __launch_bounds__(256)
void av_gemm_kernel(const float* __restrict__ attn, const float* __restrict__ KV,
                    float* __restrict__ O) {
    __shared__ float As2[32][64];
    __shared__ float Bs2[32][64];

    const int bh = blockIdx.y;
    const int b  = bh / HEADS;
    const int h  = bh % HEADS;
    const int m0 = blockIdx.x * 64;
    const int tid = threadIdx.x;
    const int tr  = (tid / 16) * 4;
    const int tc  = (tid % 16) * 4;

    const float* Abase = attn + (size_t)bh * NMM * NKV;

    float acc[4][4];
    #pragma unroll
    for (int m = 0; m < 4; m++)
        #pragma unroll
        for (int n = 0; n < 4; n++) acc[m][n] = 0.0f;

    for (int k0 = 0; k0 < NKV; k0 += 32) {
        #pragma unroll
        for (int i = 0; i < 2; i++) {
            int f  = tid + i * 256;
            int ar = f >> 3;
            int ac = (f & 7) * 4;
            float4 v = *reinterpret_cast<const float4*>(Abase + (size_t)(m0 + ar) * NKV + k0 + ac);
            As2[ac + 0][ar] = v.x;
            As2[ac + 1][ar] = v.y;
            As2[ac + 2][ar] = v.z;
            As2[ac + 3][ar] = v.w;
        }
        #pragma unroll
        for (int i = 0; i < 2; i++) {
            int f   = tid + i * 256;
            int brr = f >> 4;
            int bcc = (f & 15) * 4;
            float4 v = *reinterpret_cast<const float4*>(
                KV + (size_t)(b * NKV + k0 + brr) * KVDIM + DIM + h * HD + bcc);
            *reinterpret_cast<float4*>(&Bs2[brr][bcc]) = v;
        }
        __syncthreads();

        #pragma unroll
        for (int kk = 0; kk < 32; kk++) {
            float ra[4], rb[4];
            #pragma unroll
            for (int m = 0; m < 4; m++) ra[m] = As2[kk][tr + m];
            #pragma unroll
            for (int n = 0; n < 4; n++) rb[n] = Bs2[kk][tc + n];
            #pragma unroll
            for (int m = 0; m < 4; m++)
                #pragma unroll
                for (int n = 0; n < 4; n++) acc[m][n] += ra[m] * rb[n];
        }
        __syncthreads();
    }

    #pragma unroll
    for (int m = 0; m < 4; m++) {
        float4 v;
        v.x = acc[m][0]; v.y = acc[m][1]; v.z = acc[m][2]; v.w = acc[m][3];
        *reinterpret_cast<float4*>(&O[(size_t)(b * NMM + m0 + tr + m) * DIM + h * HD + tc]) = v;
    }
}

// ---------------------------------------------------------------------------
// Launch
// ---------------------------------------------------------------------------
extern "C" void kernel_launch(void* const* d_in, const int* in_sizes, int n_in,
                              void* d_out, int out_size) {
    const float* xmm   = (const float*)d_in[0];
    const float* xv    = (const float*)d_in[1];
    const float* xa    = (const float*)d_in[2];
    const float* Wq    = (const float*)d_in[3];
    const float* Wkv   = (const float*)d_in[4];
    const float* Wproj = (const float*)d_in[5];
    const float* bproj = (const float*)d_in[6];
    float* out = (float*)d_out;

    float *Qb, *KVb, *Ob, *attn_fb;
    cudaGetSymbolAddress((void**)&Qb,  g_Q);
    cudaGetSymbolAddress((void**)&KVb, g_KV);
    cudaGetSymbolAddress((void**)&Ob,  g_O);
    cudaGetSymbolAddress((void**)&attn_fb, g_attn_fallback);

    __nv_bfloat16 *xmm_h, *xmm_l, *xsrc_h, *xsrc_l, *O_h, *O_l;
    __nv_bfloat16 *WqT_h, *WqT_l, *WkvT_h, *WkvT_l, *WpT_h, *WpT_l;
    cudaGetSymbolAddress((void**)&xmm_h,  g_xmm_h);
    cudaGetSymbolAddress((void**)&xmm_l,  g_xmm_l);
    cudaGetSymbolAddress((void**)&xsrc_h, g_xsrc_h);
    cudaGetSymbolAddress((void**)&xsrc_l, g_xsrc_l);
    cudaGetSymbolAddress((void**)&O_h,    g_O_h);
    cudaGetSymbolAddress((void**)&O_l,    g_O_l);
    cudaGetSymbolAddress((void**)&WqT_h,  g_WqT_h);
    cudaGetSymbolAddress((void**)&WqT_l,  g_WqT_l);
    cudaGetSymbolAddress((void**)&WkvT_h, g_WkvT_h);
    cudaGetSymbolAddress((void**)&WkvT_l, g_WkvT_l);
    cudaGetSymbolAddress((void**)&WpT_h,  g_WpT_h);
    cudaGetSymbolAddress((void**)&WpT_l,  g_WpT_l);

    float* attn = (out_size >= (OUT_ELEMS + ATTN_ELEMS)) ? (out + OUT_ELEMS) : attn_fb;

    cudaFuncSetAttribute(mma_gemm_kernel,
                         cudaFuncAttributeMaxDynamicSharedMemorySize, GEMM_SMEM);
    cudaFuncSetAttribute(attn_softmax_kernel,
                         cudaFuncAttributeMaxDynamicSharedMemorySize,
                         (int)(ATT_SMEM_FLOATS * sizeof(float)));

    const int n4 = M_ROWS * DIM / 4;  // 1,572,864

    // 1) split xmm, gather+split xsrc
    split_kernel<<<(n4 + 255) / 256, 256>>>((const float4*)xmm, (uint2*)xmm_h, (uint2*)xmm_l, n4);
    gather_split_kernel<<<(n4 + 255) / 256, 256>>>(xv, xa, (uint2*)xsrc_h, (uint2*)xsrc_l);

    // 2) transpose + split weights
    {
        dim3 blk(32, 8);
        transpose_split_kernel<<<dim3(DIM / 32, DIM / 32),   blk>>>(Wq,    WqT_h,  WqT_l,  DIM, DIM);
        transpose_split_kernel<<<dim3(KVDIM / 32, DIM / 32), blk>>>(Wkv,   WkvT_h, WkvT_l, DIM, KVDIM);
        transpose_split_kernel<<<dim3(DIM / 32, DIM / 32),   blk>>>(Wproj, WpT_h,  WpT_l,  DIM, DIM);
    }

    // 3) Q = xmm @ Wq   (mma.sync split-bf16)
    mma_gemm_kernel<<<dim3(DIM / 128, M_ROWS / 128), 256, GEMM_SMEM>>>(
        xmm_h, xmm_l, WqT_h, WqT_l, nullptr, Qb, DIM, 0);

    // 4) KV = xsrc @ Wkv
    mma_gemm_kernel<<<dim3(KVDIM / 128, M_ROWS / 128), 256, GEMM_SMEM>>>(
        xsrc_h, xsrc_l, WkvT_h, WkvT_l, nullptr, KVb, KVDIM, 0);

    // 5) scores + softmax -> attn
    attn_softmax_kernel<<<dim3(NMM / 64, BS * HEADS), 256, ATT_SMEM_FLOATS * sizeof(float)>>>(
        Qb, KVb, attn);

    // 6) O = attn @ V
    av_gemm_kernel<<<dim3(NMM / 64, BS * HEADS), 256>>>(attn, KVb, Ob);

    // 7) split O, then out = O @ Wproj + bproj
    split_kernel<<<(n4 + 255) / 256, 256>>>((const float4*)Ob, (uint2*)O_h, (uint2*)O_l, n4);
    mma_gemm_kernel<<<dim3(DIM / 128, M_ROWS / 128), 256, GEMM_SMEM>>>(
        O_h, O_l, WpT_h, WpT_l, bproj, out, DIM, 1);
}

// round 5
// speedup vs baseline: 2.0122x; 1.8612x over previous
#include <cuda_runtime.h>
#include <cuda_bf16.h>
#include <math.h>
#include <stdint.h>

#define BS    32
#define NMM   256
#define NV    196
#define NA    60
#define NKV   256
#define DIM   768
#define HEADS 12
#define HD    64
#define KVDIM 1536

#define OUT_ELEMS  (BS * NMM * DIM)
#define ATTN_ELEMS (BS * HEADS * NMM * NKV)
#define M_ROWS     (BS * NMM)
#define NBH        (BS * HEADS)

// ---------------------------------------------------------------------------
// Scratch
// ---------------------------------------------------------------------------
__device__ __nv_bfloat16 g_xmm_h[M_ROWS * DIM];
__device__ __nv_bfloat16 g_xmm_l[M_ROWS * DIM];
__device__ __nv_bfloat16 g_xsrc_h[M_ROWS * DIM];
__device__ __nv_bfloat16 g_xsrc_l[M_ROWS * DIM];
__device__ __nv_bfloat16 g_WqT_h[DIM * DIM];
__device__ __nv_bfloat16 g_WqT_l[DIM * DIM];
__device__ __nv_bfloat16 g_WkvT_h[KVDIM * DIM];
__device__ __nv_bfloat16 g_WkvT_l[KVDIM * DIM];
__device__ __nv_bfloat16 g_WpT_h[DIM * DIM];
__device__ __nv_bfloat16 g_WpT_l[DIM * DIM];

__device__ __nv_bfloat16 g_Qh[NBH * NMM * HD];
__device__ __nv_bfloat16 g_Ql[NBH * NMM * HD];
__device__ __nv_bfloat16 g_Kh[NBH * NKV * HD];
__device__ __nv_bfloat16 g_Kl[NBH * NKV * HD];
__device__ __nv_bfloat16 g_Vh[NBH * NKV * HD];
__device__ __nv_bfloat16 g_Vl[NBH * NKV * HD];
__device__ __nv_bfloat16 g_Ah_s[ATTN_ELEMS];
__device__ __nv_bfloat16 g_Al_s[ATTN_ELEMS];
__device__ __nv_bfloat16 g_Oh[M_ROWS * DIM];
__device__ __nv_bfloat16 g_Ol[M_ROWS * DIM];
__device__ float g_attn_fallback[ATTN_ELEMS];

// ---------------------------------------------------------------------------
// PTX helpers (sm_80-era)
// ---------------------------------------------------------------------------
__device__ __forceinline__ uint32_t smem_u32(const void* p) {
    uint32_t a;
    asm("{ .reg .u64 t; cvta.to.shared.u64 t, %1; cvt.u32.u64 %0, t; }" : "=r"(a) : "l"(p));
    return a;
}
__device__ __forceinline__ void cp_async16(uint32_t sa, const void* gp) {
    asm volatile("cp.async.cg.shared.global [%0], [%1], 16;" :: "r"(sa), "l"(gp) : "memory");
}
__device__ __forceinline__ void cp_commit() {
    asm volatile("cp.async.commit_group;" ::: "memory");
}
template <int N>
__device__ __forceinline__ void cp_wait() {
    asm volatile("cp.async.wait_group %0;" :: "n"(N) : "memory");
}
__device__ __forceinline__ void ldsm4(uint32_t& r0, uint32_t& r1, uint32_t& r2, uint32_t& r3,
                                      uint32_t addr) {
    asm volatile("ldmatrix.sync.aligned.m8n8.x4.shared.b16 {%0,%1,%2,%3}, [%4];"
                 : "=r"(r0), "=r"(r1), "=r"(r2), "=r"(r3) : "r"(addr));
}
__device__ __forceinline__ void ldsm4t(uint32_t& r0, uint32_t& r1, uint32_t& r2, uint32_t& r3,
                                       uint32_t addr) {
    asm volatile("ldmatrix.sync.aligned.m8n8.x4.trans.shared.b16 {%0,%1,%2,%3}, [%4];"
                 : "=r"(r0), "=r"(r1), "=r"(r2), "=r"(r3) : "r"(addr));
}
__device__ __forceinline__ void mma16816(float* c, const uint32_t* a, uint32_t b0, uint32_t b1) {
    asm volatile(
        "mma.sync.aligned.m16n8k16.row.col.f32.bf16.bf16.f32 "
        "{%0,%1,%2,%3}, {%4,%5,%6,%7}, {%8,%9}, {%0,%1,%2,%3};"
        : "+f"(c[0]), "+f"(c[1]), "+f"(c[2]), "+f"(c[3])
        : "r"(a[0]), "r"(a[1]), "r"(a[2]), "r"(a[3]), "r"(b0), "r"(b1));
}

__device__ __forceinline__ void pack_hl(float f0, float f1, uint32_t& h, uint32_t& l) {
    __nv_bfloat16 h0 = __float2bfloat16(f0);
    __nv_bfloat16 h1 = __float2bfloat16(f1);
    __nv_bfloat16 l0 = __float2bfloat16(f0 - __bfloat162float(h0));
    __nv_bfloat16 l1 = __float2bfloat16(f1 - __bfloat162float(h1));
    __nv_bfloat162 hp = __halves2bfloat162(h0, h1);
    __nv_bfloat162 lp = __halves2bfloat162(l0, l1);
    h = *reinterpret_cast<uint32_t*>(&hp);
    l = *reinterpret_cast<uint32_t*>(&lp);
}

// ---------------------------------------------------------------------------
// Input conversion kernels
// ---------------------------------------------------------------------------
__device__ __forceinline__ void split4(float4 v, uint2& hv, uint2& lv) {
    uint32_t h0, l0, h1, l1;
    pack_hl(v.x, v.y, h0, l0);
    pack_hl(v.z, v.w, h1, l1);
    hv.x = h0; hv.y = h1; lv.x = l0; lv.y = l1;
}

__global__ __launch_bounds__(256)
void split_kernel(const float4* __restrict__ in, uint2* __restrict__ h,
                  uint2* __restrict__ l, int n4) {
    int i = blockIdx.x * 256 + threadIdx.x;
    if (i < n4) {
        uint2 hv, lv;
        split4(in[i], hv, lv);
        h[i] = hv;
        l[i] = lv;
    }
}

__global__ __launch_bounds__(256)
void gather_split_kernel(const float* __restrict__ xv, const float* __restrict__ xa,
                         uint2* __restrict__ h, uint2* __restrict__ l) {
    int i = blockIdx.x * 256 + threadIdx.x;
    const int C4 = DIM / 4;
    int row = i / C4;
    int c4  = i - row * C4;
    int b = row >> 8;
    int r = row & 255;
    const float4* src = (r < NV)
        ? reinterpret_cast<const float4*>(xv + (size_t)(b * NV + r) * DIM)
        : reinterpret_cast<const float4*>(xa + (size_t)(b * NA + (r - NV)) * DIM);
    uint2 hv, lv;
    split4(src[c4], hv, lv);
    h[i] = hv;
    l[i] = lv;
}

__global__ __launch_bounds__(256)
void transpose_split_kernel(const float* __restrict__ W, __nv_bfloat16* __restrict__ Th,
                            __nv_bfloat16* __restrict__ Tl, int K, int N) {
    __shared__ float t[32][33];
    int k0 = blockIdx.y * 32, n0 = blockIdx.x * 32;
    int x = threadIdx.x, y = threadIdx.y;
    #pragma unroll
    for (int i = 0; i < 32; i += 8)
        t[y + i][x] = W[(size_t)(k0 + y + i) * N + n0 + x];
    __syncthreads();
    #pragma unroll
    for (int i = 0; i < 32; i += 8) {
        float v = t[x][y + i];
        __nv_bfloat16 hi = __float2bfloat16(v);
        __nv_bfloat16 lo = __float2bfloat16(v - __bfloat162float(hi));
        size_t o = (size_t)(n0 + y + i) * K + k0 + x;
        Th[o] = hi;
        Tl[o] = lo;
    }
}

// ---------------------------------------------------------------------------
// Split-bf16 HMMA GEMM, 3-stage cp.async pipeline. 128x128 tile, BK=32.
// EPI 0: fp32 C + bias.  EPI 1: Q split epilogue.  EPI 2: KV split epilogue.
// ---------------------------------------------------------------------------
#define GK 768
#define PAD_ROW 80
#define ARR_BYTES (128 * PAD_ROW)
#define STAGE_BYTES (4 * ARR_BYTES)
#define GEMM_SMEM (3 * STAGE_BYTES)

template <int EPI>
__global__ __launch_bounds__(256, 1)
void mma_gemm_kernel(const __nv_bfloat16* __restrict__ Ah, const __nv_bfloat16* __restrict__ Al,
                     const __nv_bfloat16* __restrict__ BhT, const __nv_bfloat16* __restrict__ BlT,
                     const float* __restrict__ bias, float* __restrict__ C,
                     __nv_bfloat16* __restrict__ H1, __nv_bfloat16* __restrict__ L1,
                     __nv_bfloat16* __restrict__ H2, __nv_bfloat16* __restrict__ L2,
                     int N) {
    extern __shared__ char smem[];
    const uint32_t sb = smem_u32(smem);

    const int tid  = threadIdx.x;
    const int lane = tid & 31;
    const int wid  = tid >> 5;
    const int wr   = wid >> 2;
    const int wc   = wid & 3;
    const int m0   = blockIdx.y * 128;
    const int n0   = blockIdx.x * 128;

    const __nv_bfloat16* base0 = Ah  + (size_t)m0 * GK;
    const __nv_bfloat16* base1 = Al  + (size_t)m0 * GK;
    const __nv_bfloat16* base2 = BhT + (size_t)n0 * GK;
    const __nv_bfloat16* base3 = BlT + (size_t)n0 * GK;

    auto issue_stage = [&](int chunk, int s) {
        const int k0 = chunk << 5;
        const uint32_t sbase = sb + s * STAGE_BYTES;
        #pragma unroll
        for (int it = 0; it < 8; it++) {
            const int arr = it >> 1;
            const int j   = tid + (it & 1) * 256;
            const int row = j >> 2;
            const int q   = j & 3;
            const __nv_bfloat16* gp =
                (arr == 0 ? base0 : arr == 1 ? base1 : arr == 2 ? base2 : base3)
                + (size_t)row * GK + k0 + q * 8;
            cp_async16(sbase + arr * ARR_BYTES + row * PAD_ROW + q * 16, gp);
        }
        cp_commit();
    };

    float c[4][4][4];
    #pragma unroll
    for (int i = 0; i < 4; i++)
        #pragma unroll
        for (int j = 0; j < 4; j++)
            #pragma unroll
            for (int k = 0; k < 4; k++) c[i][j][k] = 0.0f;

    const int lr   = lane & 15;
    const int lc16 = (lane >> 4) * 16;

    issue_stage(0, 0);
    issue_stage(1, 1);

    const int nchunks = GK / 32;  // 24
    for (int i = 0; i < nchunks; i++) {
        if (i + 1 < nchunks) cp_wait<1>(); else cp_wait<0>();
        __syncthreads();
        if (i + 2 < nchunks) issue_stage(i + 2, (i + 2) % 3);

        const uint32_t st = sb + (i % 3) * STAGE_BYTES;
        const uint32_t aH_base = st + 0 * ARR_BYTES + (wr * 64 + lr) * PAD_ROW + lc16;
        const uint32_t aL_base = st + 1 * ARR_BYTES + (wr * 64 + lr) * PAD_ROW + lc16;
        const uint32_t bH_base = st + 2 * ARR_BYTES + (wc * 32 + lr) * PAD_ROW + lc16;
        const uint32_t bL_base = st + 3 * ARR_BYTES + (wc * 32 + lr) * PAD_ROW + lc16;

        #pragma unroll
        for (int kk = 0; kk < 2; kk++) {
            const uint32_t ko = kk * 32;
            uint32_t bh[4][2], bl[4][2];
            #pragma unroll
            for (int bt = 0; bt < 2; bt++) {
                uint32_t r0, r1, r2, r3;
                ldsm4(r0, r1, r2, r3, bH_base + bt * 16 * PAD_ROW + ko);
                bh[bt * 2 + 0][0] = r0; bh[bt * 2 + 0][1] = r2;
                bh[bt * 2 + 1][0] = r1; bh[bt * 2 + 1][1] = r3;
                ldsm4(r0, r1, r2, r3, bL_base + bt * 16 * PAD_ROW + ko);
                bl[bt * 2 + 0][0] = r0; bl[bt * 2 + 0][1] = r2;
                bl[bt * 2 + 1][0] = r1; bl[bt * 2 + 1][1] = r3;
            }
            #pragma unroll
            for (int mt = 0; mt < 4; mt++) {
                uint32_t aH[4], aL[4];
                ldsm4(aH[0], aH[1], aH[2], aH[3], aH_base + mt * 16 * PAD_ROW + ko);
                ldsm4(aL[0], aL[1], aL[2], aL[3], aL_base + mt * 16 * PAD_ROW + ko);
                #pragma unroll
                for (int ni = 0; ni < 4; ni++) mma16816(c[mt][ni], aH, bh[ni][0], bh[ni][1]);
                #pragma unroll
                for (int ni = 0; ni < 4; ni++) mma16816(c[mt][ni], aL, bh[ni][0], bh[ni][1]);
                #pragma unroll
                for (int ni = 0; ni < 4; ni++) mma16816(c[mt][ni], aH, bl[ni][0], bl[ni][1]);
            }
        }
    }

    // Epilogue
    const int crow0 = m0 + wr * 64 + (lane >> 2);
    const int ccol0 = n0 + wc * 32 + (lane & 3) * 2;
    #pragma unroll
    for (int mt = 0; mt < 4; mt++) {
        #pragma unroll
        for (int ni = 0; ni < 4; ni++) {
            const int cc = ccol0 + ni * 8;
            const float* cf = c[mt][ni];
            const int r0 = crow0 + mt * 16;
            const int r1 = r0 + 8;
            if (EPI == 0) {
                float b0 = 0.f, b1 = 0.f;
                if (bias) { b0 = bias[cc]; b1 = bias[cc + 1]; }
                float2 v0 = { cf[0] + b0, cf[1] + b1 };
                float2 v1 = { cf[2] + b0, cf[3] + b1 };
                *reinterpret_cast<float2*>(C + (size_t)r0 * N + cc) = v0;
                *reinterpret_cast<float2*>(C + (size_t)r1 * N + cc) = v1;
            } else if (EPI == 1) {
                // Q split: [b,h,q,d]
                const int h = cc >> 6, d = cc & 63;
                #pragma unroll
                for (int s = 0; s < 2; s++) {
                    const int r = s ? r1 : r0;
                    const int b = r >> 8, q = r & 255;
                    size_t idx = (((size_t)(b * HEADS + h)) * NMM + q) * HD + d;
                    uint32_t hh, ll;
                    pack_hl(cf[s * 2], cf[s * 2 + 1], hh, ll);
                    *reinterpret_cast<uint32_t*>(H1 + idx) = hh;
                    *reinterpret_cast<uint32_t*>(L1 + idx) = ll;
                }
            } else {
                // KV split: cols <768 -> K, else V ; [b,h,t,d]
                const bool isK = (cc < DIM);
                const int ccl = isK ? cc : cc - DIM;
                const int h = ccl >> 6, d = ccl & 63;
                __nv_bfloat16* Hd = isK ? H1 : H2;
                __nv_bfloat16* Ld = isK ? L1 : L2;
                #pragma unroll
                for (int s = 0; s < 2; s++) {
                    const int r = s ? r1 : r0;
                    const int b = r >> 8, t = r & 255;
                    size_t idx = (((size_t)(b * HEADS + h)) * NKV + t) * HD + d;
                    uint32_t hh, ll;
                    pack_hl(cf[s * 2], cf[s * 2 + 1], hh, ll);
                    *reinterpret_cast<uint32_t*>(Hd + idx) = hh;
                    *reinterpret_cast<uint32_t*>(Ld + idx) = ll;
                }
            }
        }
    }
}

// ---------------------------------------------------------------------------
// HMMA QK + softmax kernel. CTA: 128 q rows x 256 tokens of one (b,h).
// ---------------------------------------------------------------------------
#define QK_PAD 144
#define QK_QH  0
#define QK_QL  (128 * QK_PAD)
#define QK_KH  (2 * 128 * QK_PAD)
#define QK_KL  (QK_KH + 256 * QK_PAD)
#define QK_RED (QK_KH + 2 * 256 * QK_PAD)
#define QK_STG (QK_RED + 4096)
#define QK_SMEM (QK_STG + 64 * 260 * 4)

__global__ __launch_bounds__(256, 1)
void attn_qk_kernel(const __nv_bfloat16* __restrict__ Qh, const __nv_bfloat16* __restrict__ Ql,
                    const __nv_bfloat16* __restrict__ Kh, const __nv_bfloat16* __restrict__ Kl,
                    float* __restrict__ attnF,
                    __nv_bfloat16* __restrict__ Ahs, __nv_bfloat16* __restrict__ Als) {
    extern __shared__ char smem[];
    const uint32_t sb = smem_u32(smem);
    const int bh = blockIdx.y;
    const int q0 = blockIdx.x * 128;
    const int tid  = threadIdx.x;
    const int lane = tid & 31;
    const int wid  = tid >> 5;
    const int wr = wid >> 2;
    const int wc = wid & 3;

    const __nv_bfloat16* gQh = Qh + ((size_t)bh * NMM + q0) * HD;
    const __nv_bfloat16* gQl = Ql + ((size_t)bh * NMM + q0) * HD;
    const __nv_bfloat16* gKh = Kh + (size_t)bh * NKV * HD;
    const __nv_bfloat16* gKl = Kl + (size_t)bh * NKV * HD;
    for (int idx = tid; idx < 1024; idx += 256) {
        int row = idx >> 3, cq = idx & 7;
        cp_async16(sb + QK_QH + row * QK_PAD + cq * 16, gQh + row * HD + cq * 8);
        cp_async16(sb + QK_QL + row * QK_PAD + cq * 16, gQl + row * HD + cq * 8);
    }
    for (int idx = tid; idx < 2048; idx += 256) {
        int row = idx >> 3, cq = idx & 7;
        cp_async16(sb + QK_KH + row * QK_PAD + cq * 16, gKh + row * HD + cq * 8);
        cp_async16(sb + QK_KL + row * QK_PAD + cq * 16, gKl + row * HD + cq * 8);
    }
    cp_commit();
    cp_wait<0>();
    __syncthreads();

    float c[4][8][4];
    #pragma unroll
    for (int i = 0; i < 4; i++)
        #pragma unroll
        for (int j = 0; j < 8; j++)
            #pragma unroll
            for (int k = 0; k < 4; k++) c[i][j][k] = 0.0f;

    const int lr = lane & 15;
    const int lc16 = (lane >> 4) * 16;

    #pragma unroll
    for (int kk = 0; kk < 4; kk++) {
        const uint32_t ko = kk * 32;
        uint32_t aH[4][4], aL[4][4];
        #pragma unroll
        for (int mt = 0; mt < 4; mt++) {
            const uint32_t ab = sb + QK_QH + (wr * 64 + mt * 16 + lr) * QK_PAD + ko + lc16;
            ldsm4(aH[mt][0], aH[mt][1], aH[mt][2], aH[mt][3], ab);
            ldsm4(aL[mt][0], aL[mt][1], aL[mt][2], aL[mt][3], ab + QK_QL);
        }
        #pragma unroll
        for (int tb = 0; tb < 4; tb++) {
            const uint32_t bb = sb + QK_KH + (wc * 64 + tb * 16 + lr) * QK_PAD + ko + lc16;
            uint32_t h0, h1, h2, h3, l0, l1, l2, l3;
            ldsm4(h0, h1, h2, h3, bb);
            ldsm4(l0, l1, l2, l3, bb + 256 * QK_PAD);
            #pragma unroll
            for (int mt = 0; mt < 4; mt++) {
                mma16816(c[mt][tb * 2],     aH[mt], h0, h2);
                mma16816(c[mt][tb * 2],     aL[mt], h0, h2);
                mma16816(c[mt][tb * 2],     aH[mt], l0, l2);
                mma16816(c[mt][tb * 2 + 1], aH[mt], h1, h3);
                mma16816(c[mt][tb * 2 + 1], aL[mt], h1, h3);
                mma16816(c[mt][tb * 2 + 1], aH[mt], l1, l3);
            }
        }
    }

    float* pmax = reinterpret_cast<float*>(smem + QK_RED);
    float* psum = pmax + 512;
    const float scale = 0.125f;

    float rowM[4][2];
    #pragma unroll
    for (int mt = 0; mt < 4; mt++) {
        #pragma unroll
        for (int s2 = 0; s2 < 2; s2++) {
            float m = -INFINITY;
            #pragma unroll
            for (int nt = 0; nt < 8; nt++) {
                m = fmaxf(m, c[mt][nt][s2 * 2]);
                m = fmaxf(m, c[mt][nt][s2 * 2 + 1]);
            }
            m = fmaxf(m, __shfl_xor_sync(0xffffffffu, m, 1));
            m = fmaxf(m, __shfl_xor_sync(0xffffffffu, m, 2));
            if ((lane & 3) == 0) {
                int r = wr * 64 + mt * 16 + (lane >> 2) + s2 * 8;
                pmax[r * 4 + wc] = m;
            }
        }
    }
    __syncthreads();
    #pragma unroll
    for (int mt = 0; mt < 4; mt++) {
        #pragma unroll
        for (int s2 = 0; s2 < 2; s2++) {
            int r = wr * 64 + mt * 16 + (lane >> 2) + s2 * 8;
            float m = fmaxf(fmaxf(pmax[r * 4], pmax[r * 4 + 1]),
                            fmaxf(pmax[r * 4 + 2], pmax[r * 4 + 3]));
            rowM[mt][s2] = m;
        }
    }
    #pragma unroll
    for (int mt = 0; mt < 4; mt++) {
        #pragma unroll
        for (int s2 = 0; s2 < 2; s2++) {
            float m = rowM[mt][s2];
            float sum = 0.0f;
            #pragma unroll
            for (int nt = 0; nt < 8; nt++) {
                float e0 = __expf((c[mt][nt][s2 * 2]     - m) * scale);
                float e1 = __expf((c[mt][nt][s2 * 2 + 1] - m) * scale);
                c[mt][nt][s2 * 2]     = e0;
                c[mt][nt][s2 * 2 + 1] = e1;
                sum += e0 + e1;
            }
            sum += __shfl_xor_sync(0xffffffffu, sum, 1);
            sum += __shfl_xor_sync(0xffffffffu, sum, 2);
            if ((lane & 3) == 0) {
                int r = wr * 64 + mt * 16 + (lane >> 2) + s2 * 8;
                psum[r * 4 + wc] = sum;
            }
        }
    }
    __syncthreads();
    #pragma unroll
    for (int mt = 0; mt < 4; mt++) {
        #pragma unroll
        for (int s2 = 0; s2 < 2; s2++) {
            int r = wr * 64 + mt * 16 + (lane >> 2) + s2 * 8;
            float S = psum[r * 4] + psum[r * 4 + 1] + psum[r * 4 + 2] + psum[r * 4 + 3];
            float inv = 1.0f / S;
            #pragma unroll
            for (int nt = 0; nt < 8; nt++) {
                c[mt][nt][s2 * 2]     *= inv;
                c[mt][nt][s2 * 2 + 1] *= inv;
            }
        }
    }

    float* stg = reinterpret_cast<float*>(smem + QK_STG);
    for (int p = 0; p < 2; p++) {
        if (wr == p) {
            #pragma unroll
            for (int mt = 0; mt < 4; mt++) {
                #pragma unroll
                for (int nt = 0; nt < 8; nt++) {
                    int rl = mt * 16 + (lane >> 2);
                    int col = wc * 64 + nt * 8 + (lane & 3) * 2;
                    stg[rl * 260 + col]       = c[mt][nt][0];
                    stg[rl * 260 + col + 1]   = c[mt][nt][1];
                    stg[(rl + 8) * 260 + col]     = c[mt][nt][2];
                    stg[(rl + 8) * 260 + col + 1] = c[mt][nt][3];
                }
            }
        }
        __syncthreads();
        for (int idx = tid; idx < 4096; idx += 256) {
            int r = idx >> 6, c4 = (idx & 63) * 4;
            float4 v = *reinterpret_cast<float4*>(&stg[r * 260 + c4]);
            int gq = q0 + p * 64 + r;
            size_t base = ((size_t)bh * NMM + gq) * NKV + c4;
            *reinterpret_cast<float4*>(attnF + base) = v;
            uint32_t h0, l0, h1, l1;
            pack_hl(v.x, v.y, h0, l0);
            pack_hl(v.z, v.w, h1, l1);
            uint2 hv = { h0, h1 }, lv = { l0, l1 };
            *reinterpret_cast<uint2*>(Ahs + base) = hv;
            *reinterpret_cast<uint2*>(Als + base) = lv;
        }
        __syncthreads();
    }
}

// ---------------------------------------------------------------------------
// HMMA AV kernel
// ---------------------------------------------------------------------------
#define AV_APAD 80
#define AV_VPAD 144
#define AV_AH 0
#define AV_AL (128 * AV_APAD)
#define AV_VH (2 * 128 * AV_APAD)
#define AV_VL (AV_VH + 32 * AV_VPAD)
#define AV_STAGE (AV_VH + 2 * 32 * AV_VPAD)
#define AV_SMEM (3 * AV_STAGE)

__global__ __launch_bounds__(256)
void av_kernel(const __nv_bfloat16* __restrict__ Ahs, const __nv_bfloat16* __restrict__ Als,
               const __nv_bfloat16* __restrict__ Vh, const __nv_bfloat16* __restrict__ Vl,
               __nv_bfloat16* __restrict__ Oh, __nv_bfloat16* __restrict__ Ol) {
    extern __shared__ char smem[];
    const uint32_t sb = smem_u32(smem);
    const int bh = blockIdx.y;
    const int m0 = blockIdx.x * 128;
    const int b = bh / HEADS, h = bh % HEADS;
    const int tid  = threadIdx.x;
    const int lane = tid & 31;
    const int wid  = tid >> 5;
    const int wr = wid >> 2;
    const int wc = wid & 3;

    const __nv_bfloat16* gAh = Ahs + ((size_t)bh * NMM + m0) * NKV;
    const __nv_bfloat16* gAl = Als + ((size_t)bh * NMM + m0) * NKV;
    const __nv_bfloat16* gVh = Vh + (size_t)bh * NKV * HD;
    const __nv_bfloat16* gVl = Vl + (size_t)bh * NKV * HD;

    auto issue_stage = [&](int ck, int s) {
        const int k0 = ck * 32;
        const uint32_t sbase = sb + s * AV_STAGE;
        #pragma unroll
        for (int t = 0; t < 2; t++) {
            int idx = tid + t * 256;
            int row = idx >> 2, cq = idx & 3;
            cp_async16(sbase + AV_AH + row * AV_APAD + cq * 16, gAh + (size_t)row * NKV + k0 + cq * 8);
            cp_async16(sbase + AV_AL + row * AV_APAD + cq * 16, gAl + (size_t)row * NKV + k0 + cq * 8);
        }
        {
            int row = tid >> 3, cq = tid & 7;
            cp_async16(sbase + AV_VH + row * AV_VPAD + cq * 16, gVh + (size_t)(k0 + row) * HD + cq * 8);
            cp_async16(sbase + AV_VL + row * AV_VPAD + cq * 16, gVl + (size_t)(k0 + row) * HD + cq * 8);
        }
        cp_commit();
    };

    float c[4][2][4];
    #pragma unroll
    for (int i = 0; i < 4; i++)
        #pragma unroll
        for (int j = 0; j < 2; j++)
            #pragma unroll
            for (int k = 0; k < 4; k++) c[i][j][k] = 0.0f;

    const int lr = lane & 15;
    const int lc16 = (lane >> 4) * 16;

    issue_stage(0, 0);
    issue_stage(1, 1);

    const int nchunks = NKV / 32;  // 8
    for (int i = 0; i < nchunks; i++) {
        if (i + 1 < nchunks) cp_wait<1>(); else cp_wait<0>();
        __syncthreads();
        if (i + 2 < nchunks) issue_stage(i + 2, (i + 2) % 3);

        const uint32_t st = sb + (i % 3) * AV_STAGE;
        #pragma unroll
        for (int kk = 0; kk < 2; kk++) {
            const uint32_t ko = kk * 32;
            uint32_t vh0, vh1, vh2, vh3, vl0, vl1, vl2, vl3;
            const uint32_t vb = st + AV_VH + (kk * 16 + lr) * AV_VPAD + wc * 32 + lc16;
            ldsm4t(vh0, vh1, vh2, vh3, vb);
            ldsm4t(vl0, vl1, vl2, vl3, vb + 32 * AV_VPAD);
            #pragma unroll
            for (int mt = 0; mt < 4; mt++) {
                uint32_t aH[4], aL[4];
                const uint32_t ab = st + AV_AH + (wr * 64 + mt * 16 + lr) * AV_APAD + ko + lc16;
                ldsm4(aH[0], aH[1], aH[2], aH[3], ab);
                ldsm4(aL[0], aL[1], aL[2], aL[3], ab + AV_AL);
                mma16816(c[mt][0], aH, vh0, vh1);
                mma16816(c[mt][0], aL, vh0, vh1);
                mma16816(c[mt][0], aH, vl0, vl1);
                mma16816(c[mt][1], aH, vh2, vh3);
                mma16816(c[mt][1], aL, vh2, vh3);
                mma16816(c[mt][1], aH, vl2, vl3);
            }
        }
    }

    #pragma unroll
    for (int mt = 0; mt < 4; mt++) {
        #pragma unroll
        for (int nt = 0; nt < 2; nt++) {
            const int d = wc * 16 + nt * 8 + (lane & 3) * 2;
            #pragma unroll
            for (int s = 0; s < 2; s++) {
                const int q = m0 + wr * 64 + mt * 16 + (lane >> 2) + s * 8;
                size_t idx = ((size_t)(b * NMM + q)) * DIM + h * HD + d;
                uint32_t hh, ll;
                pack_hl(c[mt][nt][s * 2], c[mt][nt][s * 2 + 1], hh, ll);
                *reinterpret_cast<uint32_t*>(Oh + idx) = hh;
                *reinterpret_cast<uint32_t*>(Ol + idx) = ll;
            }
        }
    }
}

// ---------------------------------------------------------------------------
// Launch
// ---------------------------------------------------------------------------
extern "C" void kernel_launch(void* const* d_in, const int* in_sizes, int n_in,
                              void* d_out, int out_size) {
    const float* xmm   = (const float*)d_in[0];
    const float* xv    = (const float*)d_in[1];
    const float* xa    = (const float*)d_in[2];
    const float* Wq    = (const float*)d_in[3];
    const float* Wkv   = (const float*)d_in[4];
    const float* Wproj = (const float*)d_in[5];
    const float* bproj = (const float*)d_in[6];
    float* out = (float*)d_out;

    __nv_bfloat16 *xmm_h, *xmm_l, *xsrc_h, *xsrc_l;
    __nv_bfloat16 *WqT_h, *WqT_l, *WkvT_h, *WkvT_l, *WpT_h, *WpT_l;
    __nv_bfloat16 *Qh, *Ql, *Kh, *Kl, *Vh, *Vl, *Ahs, *Als, *Oh, *Ol;
    float* attn_fb;
    cudaGetSymbolAddress((void**)&xmm_h,  g_xmm_h);
    cudaGetSymbolAddress((void**)&xmm_l,  g_xmm_l);
    cudaGetSymbolAddress((void**)&xsrc_h, g_xsrc_h);
    cudaGetSymbolAddress((void**)&xsrc_l, g_xsrc_l);
    cudaGetSymbolAddress((void**)&WqT_h,  g_WqT_h);
    cudaGetSymbolAddress((void**)&WqT_l,  g_WqT_l);
    cudaGetSymbolAddress((void**)&WkvT_h, g_WkvT_h);
    cudaGetSymbolAddress((void**)&WkvT_l, g_WkvT_l);
    cudaGetSymbolAddress((void**)&WpT_h,  g_WpT_h);
    cudaGetSymbolAddress((void**)&WpT_l,  g_WpT_l);
    cudaGetSymbolAddress((void**)&Qh,  g_Qh);
    cudaGetSymbolAddress((void**)&Ql,  g_Ql);
    cudaGetSymbolAddress((void**)&Kh,  g_Kh);
    cudaGetSymbolAddress((void**)&Kl,  g_Kl);
    cudaGetSymbolAddress((void**)&Vh,  g_Vh);
    cudaGetSymbolAddress((void**)&Vl,  g_Vl);
    cudaGetSymbolAddress((void**)&Ahs, g_Ah_s);
    cudaGetSymbolAddress((void**)&Als, g_Al_s);
    cudaGetSymbolAddress((void**)&Oh,  g_Oh);
    cudaGetSymbolAddress((void**)&Ol,  g_Ol);
    cudaGetSymbolAddress((void**)&attn_fb, g_attn_fallback);

    float* attn = (out_size >= (OUT_ELEMS + ATTN_ELEMS)) ? (out + OUT_ELEMS) : attn_fb;

    cudaFuncSetAttribute(mma_gemm_kernel<0>, cudaFuncAttributeMaxDynamicSharedMemorySize, GEMM_SMEM);
    cudaFuncSetAttribute(mma_gemm_kernel<1>, cudaFuncAttributeMaxDynamicSharedMemorySize, GEMM_SMEM);
    cudaFuncSetAttribute(mma_gemm_kernel<2>, cudaFuncAttributeMaxDynamicSharedMemorySize, GEMM_SMEM);
    cudaFuncSetAttribute(attn_qk_kernel, cudaFuncAttributeMaxDynamicSharedMemorySize, QK_SMEM);
    cudaFuncSetAttribute(av_kernel, cudaFuncAttributeMaxDynamicSharedMemorySize, AV_SMEM);

    const int n4 = M_ROWS * DIM / 4;

    split_kernel<<<(n4 + 255) / 256, 256>>>((const float4*)xmm, (uint2*)xmm_h, (uint2*)xmm_l, n4);
    gather_split_kernel<<<(n4 + 255) / 256, 256>>>(xv, xa, (uint2*)xsrc_h, (uint2*)xsrc_l);
    {
        dim3 blk(32, 8);
        transpose_split_kernel<<<dim3(DIM / 32, DIM / 32),   blk>>>(Wq,    WqT_h,  WqT_l,  DIM, DIM);
        transpose_split_kernel<<<dim3(KVDIM / 32, DIM / 32), blk>>>(Wkv,   WkvT_h, WkvT_l, DIM, KVDIM);
        transpose_split_kernel<<<dim3(DIM / 32, DIM / 32),   blk>>>(Wproj, WpT_h,  WpT_l,  DIM, DIM);
    }

    mma_gemm_kernel<1><<<dim3(DIM / 128, M_ROWS / 128), 256, GEMM_SMEM>>>(
        xmm_h, xmm_l, WqT_h, WqT_l, nullptr, nullptr, Qh, Ql, nullptr, nullptr, DIM);

    mma_gemm_kernel<2><<<dim3(KVDIM / 128, M_ROWS / 128), 256, GEMM_SMEM>>>(
        xsrc_h, xsrc_l, WkvT_h, WkvT_l, nullptr, nullptr, Kh, Kl, Vh, Vl, KVDIM);

    attn_qk_kernel<<<dim3(NMM / 128, NBH), 256, QK_SMEM>>>(Qh, Ql, Kh, Kl, attn, Ahs, Als);

    av_kernel<<<dim3(NMM / 128, NBH), 256, AV_SMEM>>>(Ahs, Als, Vh, Vl, Oh, Ol);

    mma_gemm_kernel<0><<<dim3(DIM / 128, M_ROWS / 128), 256, GEMM_SMEM>>>(
        Oh, Ol, WpT_h, WpT_l, bproj, out, nullptr, nullptr, nullptr, nullptr, DIM);
}

// round 6
// speedup vs baseline: 2.8874x; 1.4350x over previous
#include <cuda_runtime.h>
#include <cuda_fp16.h>
#include <math.h>
#include <stdint.h>

#define BS    32
#define NMM   256
#define NV    196
#define NA    60
#define NKV   256
#define DIM   768
#define HEADS 12
#define HD    64
#define KVDIM 1536

#define OUT_ELEMS  (BS * NMM * DIM)
#define ATTN_ELEMS (BS * HEADS * NMM * NKV)
#define M_ROWS     (BS * NMM)
#define NBH        (BS * HEADS)

// ---------------------------------------------------------------------------
// Scratch (fp16 2-term scheme: A-side has hi+lo, B-side hi only)
// ---------------------------------------------------------------------------
__device__ __half g_xmm_h[M_ROWS * DIM];
__device__ __half g_xmm_l[M_ROWS * DIM];
__device__ __half g_xsrc_h[M_ROWS * DIM];
__device__ __half g_xsrc_l[M_ROWS * DIM];
__device__ __half g_WqT_h[DIM * DIM];
__device__ __half g_WkvT_h[KVDIM * DIM];
__device__ __half g_WpT_h[DIM * DIM];

__device__ __half g_Qh[NBH * NMM * HD];
__device__ __half g_Ql[NBH * NMM * HD];
__device__ __half g_Kh[NBH * NKV * HD];
__device__ __half g_Vh[NBH * NKV * HD];
__device__ __half g_Ph[ATTN_ELEMS];
__device__ __half g_Pl[ATTN_ELEMS];
__device__ __half g_Oh[M_ROWS * DIM];
__device__ __half g_Ol[M_ROWS * DIM];
__device__ float g_attn_fallback[ATTN_ELEMS];

// ---------------------------------------------------------------------------
// PTX helpers
// ---------------------------------------------------------------------------
__device__ __forceinline__ uint32_t smem_u32(const void* p) {
    uint32_t a;
    asm("{ .reg .u64 t; cvta.to.shared.u64 t, %1; cvt.u32.u64 %0, t; }" : "=r"(a) : "l"(p));
    return a;
}
__device__ __forceinline__ void cp_async16(uint32_t sa, const void* gp) {
    asm volatile("cp.async.cg.shared.global [%0], [%1], 16;" :: "r"(sa), "l"(gp) : "memory");
}
__device__ __forceinline__ void cp_commit() {
    asm volatile("cp.async.commit_group;" ::: "memory");
}
template <int N>
__device__ __forceinline__ void cp_wait() {
    asm volatile("cp.async.wait_group %0;" :: "n"(N) : "memory");
}
__device__ __forceinline__ void ldsm4(uint32_t& r0, uint32_t& r1, uint32_t& r2, uint32_t& r3,
                                      uint32_t addr) {
    asm volatile("ldmatrix.sync.aligned.m8n8.x4.shared.b16 {%0,%1,%2,%3}, [%4];"
                 : "=r"(r0), "=r"(r1), "=r"(r2), "=r"(r3) : "r"(addr));
}
__device__ __forceinline__ void ldsm4t(uint32_t& r0, uint32_t& r1, uint32_t& r2, uint32_t& r3,
                                       uint32_t addr) {
    asm volatile("ldmatrix.sync.aligned.m8n8.x4.trans.shared.b16 {%0,%1,%2,%3}, [%4];"
                 : "=r"(r0), "=r"(r1), "=r"(r2), "=r"(r3) : "r"(addr));
}
__device__ __forceinline__ void mma16816(float* c, const uint32_t* a, uint32_t b0, uint32_t b1) {
    asm volatile(
        "mma.sync.aligned.m16n8k16.row.col.f32.f16.f16.f32 "
        "{%0,%1,%2,%3}, {%4,%5,%6,%7}, {%8,%9}, {%0,%1,%2,%3};"
        : "+f"(c[0]), "+f"(c[1]), "+f"(c[2]), "+f"(c[3])
        : "r"(a[0]), "r"(a[1]), "r"(a[2]), "r"(a[3]), "r"(b0), "r"(b1));
}

__device__ __forceinline__ void pack_hl(float f0, float f1, uint32_t& h, uint32_t& l) {
    __half h0 = __float2half_rn(f0);
    __half h1 = __float2half_rn(f1);
    __half l0 = __float2half_rn(f0 - __half2float(h0));
    __half l1 = __float2half_rn(f1 - __half2float(h1));
    __half2 hp = __halves2half2(h0, h1);
    __half2 lp = __halves2half2(l0, l1);
    h = *reinterpret_cast<uint32_t*>(&hp);
    l = *reinterpret_cast<uint32_t*>(&lp);
}
__device__ __forceinline__ uint32_t pack_h(float f0, float f1) {
    __half2 hp = __halves2half2(__float2half_rn(f0), __float2half_rn(f1));
    return *reinterpret_cast<uint32_t*>(&hp);
}

// ---------------------------------------------------------------------------
// Input conversion kernels
// ---------------------------------------------------------------------------
__device__ __forceinline__ void split4(float4 v, uint2& hv, uint2& lv) {
    uint32_t h0, l0, h1, l1;
    pack_hl(v.x, v.y, h0, l0);
    pack_hl(v.z, v.w, h1, l1);
    hv.x = h0; hv.y = h1; lv.x = l0; lv.y = l1;
}

__global__ __launch_bounds__(256)
void split_kernel(const float4* __restrict__ in, uint2* __restrict__ h,
                  uint2* __restrict__ l, int n4) {
    int i = blockIdx.x * 256 + threadIdx.x;
    if (i < n4) {
        uint2 hv, lv;
        split4(in[i], hv, lv);
        h[i] = hv;
        l[i] = lv;
    }
}

__global__ __launch_bounds__(256)
void gather_split_kernel(const float* __restrict__ xv, const float* __restrict__ xa,
                         uint2* __restrict__ h, uint2* __restrict__ l) {
    int i = blockIdx.x * 256 + threadIdx.x;
    const int C4 = DIM / 4;
    int row = i / C4;
    int c4  = i - row * C4;
    int b = row >> 8;
    int r = row & 255;
    const float4* src = (r < NV)
        ? reinterpret_cast<const float4*>(xv + (size_t)(b * NV + r) * DIM)
        : reinterpret_cast<const float4*>(xa + (size_t)(b * NA + (r - NV)) * DIM);
    uint2 hv, lv;
    split4(src[c4], hv, lv);
    h[i] = hv;
    l[i] = lv;
}

// W[K][N] -> WT[N][K] fp16 (hi only)
__global__ __launch_bounds__(256)
void transpose_h_kernel(const float* __restrict__ W, __half* __restrict__ Th, int K, int N) {
    __shared__ float t[32][33];
    int k0 = blockIdx.y * 32, n0 = blockIdx.x * 32;
    int x = threadIdx.x, y = threadIdx.y;
    #pragma unroll
    for (int i = 0; i < 32; i += 8)
        t[y + i][x] = W[(size_t)(k0 + y + i) * N + n0 + x];
    __syncthreads();
    #pragma unroll
    for (int i = 0; i < 32; i += 8) {
        float v = t[x][y + i];
        Th[(size_t)(n0 + y + i) * K + k0 + x] = __float2half_rn(v);
    }
}

// ---------------------------------------------------------------------------
// fp16 2-term HMMA GEMM: C = (Ah+Al) @ Bh. 128x128 tile, BK=32, 3-stage.
// EPI 0: fp32 C + bias.  EPI 1: Q hi/lo split.  EPI 2: K hi / V hi.
// ---------------------------------------------------------------------------
#define GK 768
#define PAD_ROW 80
#define ARR_BYTES (128 * PAD_ROW)      // 10240
#define STAGE_BYTES (3 * ARR_BYTES)    // 30720 (Ah, Al, BhT)
#define GEMM_SMEM (3 * STAGE_BYTES)    // 92160

template <int EPI>
__global__ __launch_bounds__(256, 2)
void mma_gemm_kernel(const __half* __restrict__ Ah, const __half* __restrict__ Al,
                     const __half* __restrict__ BhT,
                     const float* __restrict__ bias, float* __restrict__ C,
                     __half* __restrict__ H1, __half* __restrict__ L1,
                     __half* __restrict__ H2,
                     int N) {
    extern __shared__ char smem[];
    const uint32_t sb = smem_u32(smem);

    const int tid  = threadIdx.x;
    const int lane = tid & 31;
    const int wid  = tid >> 5;
    const int wr   = wid >> 2;
    const int wc   = wid & 3;
    const int m0   = blockIdx.y * 128;
    const int n0   = blockIdx.x * 128;

    const __half* base0 = Ah  + (size_t)m0 * GK;
    const __half* base1 = Al  + (size_t)m0 * GK;
    const __half* base2 = BhT + (size_t)n0 * GK;

    auto issue_stage = [&](int chunk, int s) {
        const int k0 = chunk << 5;
        const uint32_t sbase = sb + s * STAGE_BYTES;
        #pragma unroll
        for (int it = 0; it < 6; it++) {
            const int arr = it >> 1;
            const int j   = tid + (it & 1) * 256;
            const int row = j >> 2;
            const int q   = j & 3;
            const __half* gp =
                (arr == 0 ? base0 : arr == 1 ? base1 : base2)
                + (size_t)row * GK + k0 + q * 8;
            cp_async16(sbase + arr * ARR_BYTES + row * PAD_ROW + q * 16, gp);
        }
        cp_commit();
    };

    float c[4][4][4];
    #pragma unroll
    for (int i = 0; i < 4; i++)
        #pragma unroll
        for (int j = 0; j < 4; j++)
            #pragma unroll
            for (int k = 0; k < 4; k++) c[i][j][k] = 0.0f;

    const int lr   = lane & 15;
    const int lc16 = (lane >> 4) * 16;

    issue_stage(0, 0);
    issue_stage(1, 1);

    const int nchunks = GK / 32;  // 24
    for (int i = 0; i < nchunks; i++) {
        if (i + 1 < nchunks) cp_wait<1>(); else cp_wait<0>();
        __syncthreads();
        if (i + 2 < nchunks) issue_stage(i + 2, (i + 2) % 3);

        const uint32_t st = sb + (i % 3) * STAGE_BYTES;
        const uint32_t aH_base = st + 0 * ARR_BYTES + (wr * 64 + lr) * PAD_ROW + lc16;
        const uint32_t aL_base = st + 1 * ARR_BYTES + (wr * 64 + lr) * PAD_ROW + lc16;
        const uint32_t bH_base = st + 2 * ARR_BYTES + (wc * 32 + lr) * PAD_ROW + lc16;

        #pragma unroll
        for (int kk = 0; kk < 2; kk++) {
            const uint32_t ko = kk * 32;
            uint32_t bh[4][2];
            #pragma unroll
            for (int bt = 0; bt < 2; bt++) {
                uint32_t r0, r1, r2, r3;
                ldsm4(r0, r1, r2, r3, bH_base + bt * 16 * PAD_ROW + ko);
                bh[bt * 2 + 0][0] = r0; bh[bt * 2 + 0][1] = r2;
                bh[bt * 2 + 1][0] = r1; bh[bt * 2 + 1][1] = r3;
            }
            #pragma unroll
            for (int mt = 0; mt < 4; mt++) {
                uint32_t aH[4], aL[4];
                ldsm4(aH[0], aH[1], aH[2], aH[3], aH_base + mt * 16 * PAD_ROW + ko);
                ldsm4(aL[0], aL[1], aL[2], aL[3], aL_base + mt * 16 * PAD_ROW + ko);
                #pragma unroll
                for (int ni = 0; ni < 4; ni++) mma16816(c[mt][ni], aH, bh[ni][0], bh[ni][1]);
                #pragma unroll
                for (int ni = 0; ni < 4; ni++) mma16816(c[mt][ni], aL, bh[ni][0], bh[ni][1]);
            }
        }
    }

    // Epilogue
    const int crow0 = m0 + wr * 64 + (lane >> 2);
    const int ccol0 = n0 + wc * 32 + (lane & 3) * 2;
    #pragma unroll
    for (int mt = 0; mt < 4; mt++) {
        #pragma unroll
        for (int ni = 0; ni < 4; ni++) {
            const int cc = ccol0 + ni * 8;
            const float* cf = c[mt][ni];
            const int r0 = crow0 + mt * 16;
            const int r1 = r0 + 8;
            if (EPI == 0) {
                float b0 = 0.f, b1 = 0.f;
                if (bias) { b0 = bias[cc]; b1 = bias[cc + 1]; }
                float2 v0 = { cf[0] + b0, cf[1] + b1 };
                float2 v1 = { cf[2] + b0, cf[3] + b1 };
                *reinterpret_cast<float2*>(C + (size_t)r0 * N + cc) = v0;
                *reinterpret_cast<float2*>(C + (size_t)r1 * N + cc) = v1;
            } else if (EPI == 1) {
                // Q split: [b,h,q,d] hi+lo
                const int h = cc >> 6, d = cc & 63;
                #pragma unroll
                for (int s = 0; s < 2; s++) {
                    const int r = s ? r1 : r0;
                    const int b = r >> 8, q = r & 255;
                    size_t idx = (((size_t)(b * HEADS + h)) * NMM + q) * HD + d;
                    uint32_t hh, ll;
                    pack_hl(cf[s * 2], cf[s * 2 + 1], hh, ll);
                    *reinterpret_cast<uint32_t*>(H1 + idx) = hh;
                    *reinterpret_cast<uint32_t*>(L1 + idx) = ll;
                }
            } else {
                // KV: cols <768 -> K (hi only), else V (hi only) ; [b,h,t,d]
                const bool isK = (cc < DIM);
                const int ccl = isK ? cc : cc - DIM;
                const int h = ccl >> 6, d = ccl & 63;
                __half* Hd = isK ? H1 : H2;
                #pragma unroll
                for (int s = 0; s < 2; s++) {
                    const int r = s ? r1 : r0;
                    const int b = r >> 8, t = r & 255;
                    size_t idx = (((size_t)(b * HEADS + h)) * NKV + t) * HD + d;
                    *reinterpret_cast<uint32_t*>(Hd + idx) = pack_h(cf[s * 2], cf[s * 2 + 1]);
                }
            }
        }
    }
}

// ---------------------------------------------------------------------------
// HMMA QK + softmax kernel: S = (Qh+Ql)Kh^T, softmax, write attn fp32 + P hi/lo.
// ---------------------------------------------------------------------------
#define QK_PAD 144
#define QK_QH  0
#define QK_QL  (128 * QK_PAD)
#define QK_KH  (2 * 128 * QK_PAD)              // 36864
#define QK_RED (QK_KH + 256 * QK_PAD)          // 73728
#define QK_STG (QK_RED + 4096)                 // 77824
#define QK_SMEM (QK_STG + 64 * 260 * 4)        // 144384

__global__ __launch_bounds__(256, 1)
void attn_qk_kernel(const __half* __restrict__ Qh, const __half* __restrict__ Ql,
                    const __half* __restrict__ Kh,
                    float* __restrict__ attnF,
                    __half* __restrict__ Ph, __half* __restrict__ Pl) {
    extern __shared__ char smem[];
    const uint32_t sb = smem_u32(smem);
    const int bh = blockIdx.y;
    const int q0 = blockIdx.x * 128;
    const int tid  = threadIdx.x;
    const int lane = tid & 31;
    const int wid  = tid >> 5;
    const int wr = wid >> 2;
    const int wc = wid & 3;

    const __half* gQh = Qh + ((size_t)bh * NMM + q0) * HD;
    const __half* gQl = Ql + ((size_t)bh * NMM + q0) * HD;
    const __half* gKh = Kh + (size_t)bh * NKV * HD;
    for (int idx = tid; idx < 1024; idx += 256) {
        int row = idx >> 3, cq = idx & 7;
        cp_async16(sb + QK_QH + row * QK_PAD + cq * 16, gQh + row * HD + cq * 8);
        cp_async16(sb + QK_QL + row * QK_PAD + cq * 16, gQl + row * HD + cq * 8);
    }
    for (int idx = tid; idx < 2048; idx += 256) {
        int row = idx >> 3, cq = idx & 7;
        cp_async16(sb + QK_KH + row * QK_PAD + cq * 16, gKh + row * HD + cq * 8);
    }
    cp_commit();
    cp_wait<0>();
    __syncthreads();

    float c[4][8][4];
    #pragma unroll
    for (int i = 0; i < 4; i++)
        #pragma unroll
        for (int j = 0; j < 8; j++)
            #pragma unroll
            for (int k = 0; k < 4; k++) c[i][j][k] = 0.0f;

    const int lr = lane & 15;
    const int lc16 = (lane >> 4) * 16;

    #pragma unroll
    for (int kk = 0; kk < 4; kk++) {
        const uint32_t ko = kk * 32;
        uint32_t aH[4][4], aL[4][4];
        #pragma unroll
        for (int mt = 0; mt < 4; mt++) {
            const uint32_t ab = sb + QK_QH + (wr * 64 + mt * 16 + lr) * QK_PAD + ko + lc16;
            ldsm4(aH[mt][0], aH[mt][1], aH[mt][2], aH[mt][3], ab);
            ldsm4(aL[mt][0], aL[mt][1], aL[mt][2], aL[mt][3], ab + QK_QL);
        }
        #pragma unroll
        for (int tb = 0; tb < 4; tb++) {
            const uint32_t bb = sb + QK_KH + (wc * 64 + tb * 16 + lr) * QK_PAD + ko + lc16;
            uint32_t h0, h1, h2, h3;
            ldsm4(h0, h1, h2, h3, bb);
            #pragma unroll
            for (int mt = 0; mt < 4; mt++) {
                mma16816(c[mt][tb * 2],     aH[mt], h0, h2);
                mma16816(c[mt][tb * 2],     aL[mt], h0, h2);
                mma16816(c[mt][tb * 2 + 1], aH[mt], h1, h3);
                mma16816(c[mt][tb * 2 + 1], aL[mt], h1, h3);
            }
        }
    }

    float* pmax = reinterpret_cast<float*>(smem + QK_RED);
    float* psum = pmax + 512;
    const float scale = 0.125f;

    float rowM[4][2];
    #pragma unroll
    for (int mt = 0; mt < 4; mt++) {
        #pragma unroll
        for (int s2 = 0; s2 < 2; s2++) {
            float m = -INFINITY;
            #pragma unroll
            for (int nt = 0; nt < 8; nt++) {
                m = fmaxf(m, c[mt][nt][s2 * 2]);
                m = fmaxf(m, c[mt][nt][s2 * 2 + 1]);
            }
            m = fmaxf(m, __shfl_xor_sync(0xffffffffu, m, 1));
            m = fmaxf(m, __shfl_xor_sync(0xffffffffu, m, 2));
            if ((lane & 3) == 0) {
                int r = wr * 64 + mt * 16 + (lane >> 2) + s2 * 8;
                pmax[r * 4 + wc] = m;
            }
        }
    }
    __syncthreads();
    #pragma unroll
    for (int mt = 0; mt < 4; mt++) {
        #pragma unroll
        for (int s2 = 0; s2 < 2; s2++) {
            int r = wr * 64 + mt * 16 + (lane >> 2) + s2 * 8;
            rowM[mt][s2] = fmaxf(fmaxf(pmax[r * 4], pmax[r * 4 + 1]),
                                 fmaxf(pmax[r * 4 + 2], pmax[r * 4 + 3]));
        }
    }
    #pragma unroll
    for (int mt = 0; mt < 4; mt++) {
        #pragma unroll
        for (int s2 = 0; s2 < 2; s2++) {
            float m = rowM[mt][s2];
            float sum = 0.0f;
            #pragma unroll
            for (int nt = 0; nt < 8; nt++) {
                float e0 = __expf((c[mt][nt][s2 * 2]     - m) * scale);
                float e1 = __expf((c[mt][nt][s2 * 2 + 1] - m) * scale);
                c[mt][nt][s2 * 2]     = e0;
                c[mt][nt][s2 * 2 + 1] = e1;
                sum += e0 + e1;
            }
            sum += __shfl_xor_sync(0xffffffffu, sum, 1);
            sum += __shfl_xor_sync(0xffffffffu, sum, 2);
            if ((lane & 3) == 0) {
                int r = wr * 64 + mt * 16 + (lane >> 2) + s2 * 8;
                psum[r * 4 + wc] = sum;
            }
        }
    }
    __syncthreads();
    #pragma unroll
    for (int mt = 0; mt < 4; mt++) {
        #pragma unroll
        for (int s2 = 0; s2 < 2; s2++) {
            int r = wr * 64 + mt * 16 + (lane >> 2) + s2 * 8;
            float S = psum[r * 4] + psum[r * 4 + 1] + psum[r * 4 + 2] + psum[r * 4 + 3];
            float inv = 1.0f / S;
            #pragma unroll
            for (int nt = 0; nt < 8; nt++) {
                c[mt][nt][s2 * 2]     *= inv;
                c[mt][nt][s2 * 2 + 1] *= inv;
            }
        }
    }

    float* stg = reinterpret_cast<float*>(smem + QK_STG);
    for (int p = 0; p < 2; p++) {
        if (wr == p) {
            #pragma unroll
            for (int mt = 0; mt < 4; mt++) {
                #pragma unroll
                for (int nt = 0; nt < 8; nt++) {
                    int rl = mt * 16 + (lane >> 2);
                    int col = wc * 64 + nt * 8 + (lane & 3) * 2;
                    stg[rl * 260 + col]       = c[mt][nt][0];
                    stg[rl * 260 + col + 1]   = c[mt][nt][1];
                    stg[(rl + 8) * 260 + col]     = c[mt][nt][2];
                    stg[(rl + 8) * 260 + col + 1] = c[mt][nt][3];
                }
            }
        }
        __syncthreads();
        for (int idx = tid; idx < 4096; idx += 256) {
            int r = idx >> 6, c4 = (idx & 63) * 4;
            float4 v = *reinterpret_cast<float4*>(&stg[r * 260 + c4]);
            int gq = q0 + p * 64 + r;
            size_t base = ((size_t)bh * NMM + gq) * NKV + c4;
            *reinterpret_cast<float4*>(attnF + base) = v;
            uint32_t h0, l0, h1, l1;
            pack_hl(v.x, v.y, h0, l0);
            pack_hl(v.z, v.w, h1, l1);
            uint2 hv = { h0, h1 }, lv = { l0, l1 };
            *reinterpret_cast<uint2*>(Ph + base) = hv;
            *reinterpret_cast<uint2*>(Pl + base) = lv;
        }
        __syncthreads();
    }
}

// ---------------------------------------------------------------------------
// HMMA AV kernel: O = (Ph+Pl) @ Vh, 3-stage pipeline, trans-ldmatrix V.
// ---------------------------------------------------------------------------
#define AV_APAD 80
#define AV_VPAD 144
#define AV_AH 0
#define AV_AL (128 * AV_APAD)                 // 10240
#define AV_VH (2 * 128 * AV_APAD)             // 20480
#define AV_STAGE (AV_VH + 32 * AV_VPAD)       // 25088
#define AV_SMEM (3 * AV_STAGE)                // 75264

__global__ __launch_bounds__(256, 2)
void av_kernel(const __half* __restrict__ Ph, const __half* __restrict__ Pl,
               const __half* __restrict__ Vh,
               __half* __restrict__ Oh, __half* __restrict__ Ol) {
    extern __shared__ char smem[];
    const uint32_t sb = smem_u32(smem);
    const int bh = blockIdx.y;
    const int m0 = blockIdx.x * 128;
    const int b = bh / HEADS, h = bh % HEADS;
    const int tid  = threadIdx.x;
    const int lane = tid & 31;
    const int wid  = tid >> 5;
    const int wr = wid >> 2;
    const int wc = wid & 3;

    const __half* gAh = Ph + ((size_t)bh * NMM + m0) * NKV;
    const __half* gAl = Pl + ((size_t)bh * NMM + m0) * NKV;
    const __half* gVh = Vh + (size_t)bh * NKV * HD;

    auto issue_stage = [&](int ck, int s) {
        const int k0 = ck * 32;
        const uint32_t sbase = sb + s * AV_STAGE;
        #pragma unroll
        for (int t = 0; t < 2; t++) {
            int idx = tid + t * 256;
            int row = idx >> 2, cq = idx & 3;
            cp_async16(sbase + AV_AH + row * AV_APAD + cq * 16, gAh + (size_t)row * NKV + k0 + cq * 8);
            cp_async16(sbase + AV_AL + row * AV_APAD + cq * 16, gAl + (size_t)row * NKV + k0 + cq * 8);
        }
        {
            int row = tid >> 3, cq = tid & 7;
            cp_async16(sbase + AV_VH + row * AV_VPAD + cq * 16, gVh + (size_t)(k0 + row) * HD + cq * 8);
        }
        cp_commit();
    };

    float c[4][2][4];
    #pragma unroll
    for (int i = 0; i < 4; i++)
        #pragma unroll
        for (int j = 0; j < 2; j++)
            #pragma unroll
            for (int k = 0; k < 4; k++) c[i][j][k] = 0.0f;

    const int lr = lane & 15;
    const int lc16 = (lane >> 4) * 16;

    issue_stage(0, 0);
    issue_stage(1, 1);

    const int nchunks = NKV / 32;  // 8
    for (int i = 0; i < nchunks; i++) {
        if (i + 1 < nchunks) cp_wait<1>(); else cp_wait<0>();
        __syncthreads();
        if (i + 2 < nchunks) issue_stage(i + 2, (i + 2) % 3);

        const uint32_t st = sb + (i % 3) * AV_STAGE;
        #pragma unroll
        for (int kk = 0; kk < 2; kk++) {
            const uint32_t ko = kk * 32;
            uint32_t vh0, vh1, vh2, vh3;
            const uint32_t vb = st + AV_VH + (kk * 16 + lr) * AV_VPAD + wc * 32 + lc16;
            ldsm4t(vh0, vh1, vh2, vh3, vb);
            #pragma unroll
            for (int mt = 0; mt < 4; mt++) {
                uint32_t aH[4], aL[4];
                const uint32_t ab = st + AV_AH + (wr * 64 + mt * 16 + lr) * AV_APAD + ko + lc16;
                ldsm4(aH[0], aH[1], aH[2], aH[3], ab);
                ldsm4(aL[0], aL[1], aL[2], aL[3], ab + AV_AL);
                mma16816(c[mt][0], aH, vh0, vh1);
                mma16816(c[mt][0], aL, vh0, vh1);
                mma16816(c[mt][1], aH, vh2, vh3);
                mma16816(c[mt][1], aL, vh2, vh3);
            }
        }
    }

    #pragma unroll
    for (int mt = 0; mt < 4; mt++) {
        #pragma unroll
        for (int nt = 0; nt < 2; nt++) {
            const int d = wc * 16 + nt * 8 + (lane & 3) * 2;
            #pragma unroll
            for (int s = 0; s < 2; s++) {
                const int q = m0 + wr * 64 + mt * 16 + (lane >> 2) + s * 8;
                size_t idx = ((size_t)(b * NMM + q)) * DIM + h * HD + d;
                uint32_t hh, ll;
                pack_hl(c[mt][nt][s * 2], c[mt][nt][s * 2 + 1], hh, ll);
                *reinterpret_cast<uint32_t*>(Oh + idx) = hh;
                *reinterpret_cast<uint32_t*>(Ol + idx) = ll;
            }
        }
    }
}

// ---------------------------------------------------------------------------
// Launch
// ---------------------------------------------------------------------------
extern "C" void kernel_launch(void* const* d_in, const int* in_sizes, int n_in,
                              void* d_out, int out_size) {
    const float* xmm   = (const float*)d_in[0];
    const float* xv    = (const float*)d_in[1];
    const float* xa    = (const float*)d_in[2];
    const float* Wq    = (const float*)d_in[3];
    const float* Wkv   = (const float*)d_in[4];
    const float* Wproj = (const float*)d_in[5];
    const float* bproj = (const float*)d_in[6];
    float* out = (float*)d_out;

    __half *xmm_h, *xmm_l, *xsrc_h, *xsrc_l;
    __half *WqT_h, *WkvT_h, *WpT_h;
    __half *Qh, *Ql, *Kh, *Vh, *Ph, *Pl, *Oh, *Ol;
    float* attn_fb;
    cudaGetSymbolAddress((void**)&xmm_h,  g_xmm_h);
    cudaGetSymbolAddress((void**)&xmm_l,  g_xmm_l);
    cudaGetSymbolAddress((void**)&xsrc_h, g_xsrc_h);
    cudaGetSymbolAddress((void**)&xsrc_l, g_xsrc_l);
    cudaGetSymbolAddress((void**)&WqT_h,  g_WqT_h);
    cudaGetSymbolAddress((void**)&WkvT_h, g_WkvT_h);
    cudaGetSymbolAddress((void**)&WpT_h,  g_WpT_h);
    cudaGetSymbolAddress((void**)&Qh,  g_Qh);
    cudaGetSymbolAddress((void**)&Ql,  g_Ql);
    cudaGetSymbolAddress((void**)&Kh,  g_Kh);
    cudaGetSymbolAddress((void**)&Vh,  g_Vh);
    cudaGetSymbolAddress((void**)&Ph,  g_Ph);
    cudaGetSymbolAddress((void**)&Pl,  g_Pl);
    cudaGetSymbolAddress((void**)&Oh,  g_Oh);
    cudaGetSymbolAddress((void**)&Ol,  g_Ol);
    cudaGetSymbolAddress((void**)&attn_fb, g_attn_fallback);

    float* attn = (out_size >= (OUT_ELEMS + ATTN_ELEMS)) ? (out + OUT_ELEMS) : attn_fb;

    cudaFuncSetAttribute(mma_gemm_kernel<0>, cudaFuncAttributeMaxDynamicSharedMemorySize, GEMM_SMEM);
    cudaFuncSetAttribute(mma_gemm_kernel<1>, cudaFuncAttributeMaxDynamicSharedMemorySize, GEMM_SMEM);
    cudaFuncSetAttribute(mma_gemm_kernel<2>, cudaFuncAttributeMaxDynamicSharedMemorySize, GEMM_SMEM);
    cudaFuncSetAttribute(attn_qk_kernel, cudaFuncAttributeMaxDynamicSharedMemorySize, QK_SMEM);
    cudaFuncSetAttribute(av_kernel, cudaFuncAttributeMaxDynamicSharedMemorySize, AV_SMEM);

    const int n4 = M_ROWS * DIM / 4;

    split_kernel<<<(n4 + 255) / 256, 256>>>((const float4*)xmm, (uint2*)xmm_h, (uint2*)xmm_l, n4);
    gather_split_kernel<<<(n4 + 255) / 256, 256>>>(xv, xa, (uint2*)xsrc_h, (uint2*)xsrc_l);
    {
        dim3 blk(32, 8);
        transpose_h_kernel<<<dim3(DIM / 32, DIM / 32),   blk>>>(Wq,    WqT_h,  DIM, DIM);
        transpose_h_kernel<<<dim3(KVDIM / 32, DIM / 32), blk>>>(Wkv,   WkvT_h, DIM, KVDIM);
        transpose_h_kernel<<<dim3(DIM / 32, DIM / 32),   blk>>>(Wproj, WpT_h,  DIM, DIM);
    }

    // Q projection -> Qh/Ql
    mma_gemm_kernel<1><<<dim3(DIM / 128, M_ROWS / 128), 256, GEMM_SMEM>>>(
        xmm_h, xmm_l, WqT_h, nullptr, nullptr, Qh, Ql, nullptr, DIM);

    // KV projection -> Kh, Vh
    mma_gemm_kernel<2><<<dim3(KVDIM / 128, M_ROWS / 128), 256, GEMM_SMEM>>>(
        xsrc_h, xsrc_l, WkvT_h, nullptr, nullptr, Kh, nullptr, Vh, KVDIM);

    // QK + softmax -> attn fp32 + P hi/lo
    attn_qk_kernel<<<dim3(NMM / 128, NBH), 256, QK_SMEM>>>(Qh, Ql, Kh, attn, Ph, Pl);

    // AV -> O hi/lo
    av_kernel<<<dim3(NMM / 128, NBH), 256, AV_SMEM>>>(Ph, Pl, Vh, Oh, Ol);

    // Output projection
    mma_gemm_kernel<0><<<dim3(DIM / 128, M_ROWS / 128), 256, GEMM_SMEM>>>(
        Oh, Ol, WpT_h, bproj, out, nullptr, nullptr, nullptr, DIM);
}

// round 7
// speedup vs baseline: 3.4297x; 1.1878x over previous
#include <cuda_runtime.h>
#include <cuda_fp16.h>
#include <math.h>
#include <stdint.h>

#define BS    32
#define NMM   256
#define NV    196
#define NA    60
#define NKV   256
#define DIM   768
#define HEADS 12
#define HD    64
#define KVDIM 1536

#define OUT_ELEMS  (BS * NMM * DIM)
#define ATTN_ELEMS (BS * HEADS * NMM * NKV)
#define M_ROWS     (BS * NMM)
#define NBH        (BS * HEADS)

// ---------------------------------------------------------------------------
// Scratch
// ---------------------------------------------------------------------------
__device__ __half g_xmm_h[M_ROWS * DIM];
__device__ __half g_xmm_l[M_ROWS * DIM];
__device__ __half g_xsrc_h[M_ROWS * DIM];
__device__ __half g_xsrc_l[M_ROWS * DIM];
__device__ __half g_WqT_h[DIM * DIM];
__device__ __half g_WkvT_h[KVDIM * DIM];
__device__ __half g_WpT_h[DIM * DIM];

__device__ __half g_Qh[NBH * NMM * HD];
__device__ __half g_Ql[NBH * NMM * HD];
__device__ __half g_Kh[NBH * NKV * HD];
__device__ __half g_Vh[NBH * NKV * HD];
__device__ __half g_Ph[ATTN_ELEMS];
__device__ __half g_Oh[M_ROWS * DIM];
__device__ __half g_Ol[M_ROWS * DIM];
__device__ float g_attn_fallback[ATTN_ELEMS];

// ---------------------------------------------------------------------------
// PTX helpers
// ---------------------------------------------------------------------------
__device__ __forceinline__ uint32_t smem_u32(const void* p) {
    uint32_t a;
    asm("{ .reg .u64 t; cvta.to.shared.u64 t, %1; cvt.u32.u64 %0, t; }" : "=r"(a) : "l"(p));
    return a;
}
__device__ __forceinline__ void cp_async16(uint32_t sa, const void* gp) {
    asm volatile("cp.async.cg.shared.global [%0], [%1], 16;" :: "r"(sa), "l"(gp) : "memory");
}
__device__ __forceinline__ void cp_commit() {
    asm volatile("cp.async.commit_group;" ::: "memory");
}
template <int N>
__device__ __forceinline__ void cp_wait() {
    asm volatile("cp.async.wait_group %0;" :: "n"(N) : "memory");
}
__device__ __forceinline__ void ldsm4(uint32_t& r0, uint32_t& r1, uint32_t& r2, uint32_t& r3,
                                      uint32_t addr) {
    asm volatile("ldmatrix.sync.aligned.m8n8.x4.shared.b16 {%0,%1,%2,%3}, [%4];"
                 : "=r"(r0), "=r"(r1), "=r"(r2), "=r"(r3) : "r"(addr));
}
__device__ __forceinline__ void ldsm4t(uint32_t& r0, uint32_t& r1, uint32_t& r2, uint32_t& r3,
                                       uint32_t addr) {
    asm volatile("ldmatrix.sync.aligned.m8n8.x4.trans.shared.b16 {%0,%1,%2,%3}, [%4];"
                 : "=r"(r0), "=r"(r1), "=r"(r2), "=r"(r3) : "r"(addr));
}
__device__ __forceinline__ void mma16816(float* c, const uint32_t* a, uint32_t b0, uint32_t b1) {
    asm volatile(
        "mma.sync.aligned.m16n8k16.row.col.f32.f16.f16.f32 "
        "{%0,%1,%2,%3}, {%4,%5,%6,%7}, {%8,%9}, {%0,%1,%2,%3};"
        : "+f"(c[0]), "+f"(c[1]), "+f"(c[2]), "+f"(c[3])
        : "r"(a[0]), "r"(a[1]), "r"(a[2]), "r"(a[3]), "r"(b0), "r"(b1));
}

__device__ __forceinline__ void pack_hl(float f0, float f1, uint32_t& h, uint32_t& l) {
    __half h0 = __float2half_rn(f0);
    __half h1 = __float2half_rn(f1);
    __half l0 = __float2half_rn(f0 - __half2float(h0));
    __half l1 = __float2half_rn(f1 - __half2float(h1));
    __half2 hp = __halves2half2(h0, h1);
    __half2 lp = __halves2half2(l0, l1);
    h = *reinterpret_cast<uint32_t*>(&hp);
    l = *reinterpret_cast<uint32_t*>(&lp);
}
__device__ __forceinline__ uint32_t pack_h(float f0, float f1) {
    __half2 hp = __halves2half2(__float2half_rn(f0), __float2half_rn(f1));
    return *reinterpret_cast<uint32_t*>(&hp);
}

// ---------------------------------------------------------------------------
// Input conversion
// ---------------------------------------------------------------------------
__device__ __forceinline__ void split4(float4 v, uint2& hv, uint2& lv) {
    uint32_t h0, l0, h1, l1;
    pack_hl(v.x, v.y, h0, l0);
    pack_hl(v.z, v.w, h1, l1);
    hv.x = h0; hv.y = h1; lv.x = l0; lv.y = l1;
}

#define N4 (M_ROWS * DIM / 4)

__global__ __launch_bounds__(256)
void prep_inputs_kernel(const float4* __restrict__ xmm,
                        const float* __restrict__ xv, const float* __restrict__ xa,
                        uint2* __restrict__ xmm_h, uint2* __restrict__ xmm_l,
                        uint2* __restrict__ xsrc_h, uint2* __restrict__ xsrc_l) {
    int i = blockIdx.x * 256 + threadIdx.x;
    if (i < N4) {
        uint2 hv, lv;
        split4(xmm[i], hv, lv);
        xmm_h[i] = hv;
        xmm_l[i] = lv;
    } else {
        i -= N4;
        const int C4 = DIM / 4;
        int row = i / C4;
        int c4  = i - row * C4;
        int b = row >> 8;
        int r = row & 255;
        const float4* src = (r < NV)
            ? reinterpret_cast<const float4*>(xv + (size_t)(b * NV + r) * DIM)
            : reinterpret_cast<const float4*>(xa + (size_t)(b * NA + (r - NV)) * DIM);
        uint2 hv, lv;
        split4(src[c4], hv, lv);
        xsrc_h[i] = hv;
        xsrc_l[i] = lv;
    }
}

__global__ __launch_bounds__(256)
void transpose_h_kernel(const float* __restrict__ W, __half* __restrict__ Th, int K, int N) {
    __shared__ float t[32][33];
    int k0 = blockIdx.y * 32, n0 = blockIdx.x * 32;
    int x = threadIdx.x, y = threadIdx.y;
    #pragma unroll
    for (int i = 0; i < 32; i += 8)
        t[y + i][x] = W[(size_t)(k0 + y + i) * N + n0 + x];
    __syncthreads();
    #pragma unroll
    for (int i = 0; i < 32; i += 8)
        Th[(size_t)(n0 + y + i) * K + k0 + x] = __float2half_rn(t[x][y + i]);
}

// ---------------------------------------------------------------------------
// fp16 2-term HMMA GEMM, runtime epilogue select.
// mode 0: out-proj (epi 0, bias, fp32 C). mode 1: merged Q+KV projection
//   (blockIdx.x < 6 -> Q epi 1; else KV epi 2).
// ---------------------------------------------------------------------------
#define GK 768
#define PAD_ROW 80
#define ARR_BYTES (128 * PAD_ROW)
#define STAGE_BYTES (3 * ARR_BYTES)
#define GEMM_SMEM (3 * STAGE_BYTES)

__global__ __launch_bounds__(256, 2)
void proj_kernel(int mode,
                 const __half* __restrict__ A0h, const __half* __restrict__ A0l,
                 const __half* __restrict__ B0T,
                 const __half* __restrict__ A1h, const __half* __restrict__ A1l,
                 const __half* __restrict__ B1T,
                 const float* __restrict__ bias, float* __restrict__ C,
                 __half* __restrict__ QhO, __half* __restrict__ QlO,
                 __half* __restrict__ KhO, __half* __restrict__ VhO) {
    extern __shared__ char smem[];
    const uint32_t sb = smem_u32(smem);

    const int tid  = threadIdx.x;
    const int lane = tid & 31;
    const int wid  = tid >> 5;
    const int wr   = wid >> 2;
    const int wc   = wid & 3;
    const int m0   = blockIdx.y * 128;

    int epi, n0;
    const __half *Ahp, *Alp, *BTp;
    if (mode == 0) {
        epi = 0; Ahp = A0h; Alp = A0l; BTp = B0T; n0 = blockIdx.x * 128;
    } else if (blockIdx.x < 6) {
        epi = 1; Ahp = A0h; Alp = A0l; BTp = B0T; n0 = blockIdx.x * 128;
    } else {
        epi = 2; Ahp = A1h; Alp = A1l; BTp = B1T; n0 = (blockIdx.x - 6) * 128;
    }

    const __half* base0 = Ahp + (size_t)m0 * GK;
    const __half* base1 = Alp + (size_t)m0 * GK;
    const __half* base2 = BTp + (size_t)n0 * GK;

    auto issue_stage = [&](int chunk, int s) {
        const int k0 = chunk << 5;
        const uint32_t sbase = sb + s * STAGE_BYTES;
        #pragma unroll
        for (int it = 0; it < 6; it++) {
            const int arr = it >> 1;
            const int j   = tid + (it & 1) * 256;
            const int row = j >> 2;
            const int q   = j & 3;
            const __half* gp =
                (arr == 0 ? base0 : arr == 1 ? base1 : base2)
                + (size_t)row * GK + k0 + q * 8;
            cp_async16(sbase + arr * ARR_BYTES + row * PAD_ROW + q * 16, gp);
        }
        cp_commit();
    };

    float c[4][4][4];
    #pragma unroll
    for (int i = 0; i < 4; i++)
        #pragma unroll
        for (int j = 0; j < 4; j++)
            #pragma unroll
            for (int k = 0; k < 4; k++) c[i][j][k] = 0.0f;

    const int lr   = lane & 15;
    const int lc16 = (lane >> 4) * 16;

    issue_stage(0, 0);
    issue_stage(1, 1);

    const int nchunks = GK / 32;  // 24
    for (int i = 0; i < nchunks; i++) {
        if (i + 1 < nchunks) cp_wait<1>(); else cp_wait<0>();
        __syncthreads();
        if (i + 2 < nchunks) issue_stage(i + 2, (i + 2) % 3);

        const uint32_t st = sb + (i % 3) * STAGE_BYTES;
        const uint32_t aH_base = st + 0 * ARR_BYTES + (wr * 64 + lr) * PAD_ROW + lc16;
        const uint32_t aL_base = st + 1 * ARR_BYTES + (wr * 64 + lr) * PAD_ROW + lc16;
        const uint32_t bH_base = st + 2 * ARR_BYTES + (wc * 32 + lr) * PAD_ROW + lc16;

        #pragma unroll
        for (int kk = 0; kk < 2; kk++) {
            const uint32_t ko = kk * 32;
            uint32_t bh[4][2];
            #pragma unroll
            for (int bt = 0; bt < 2; bt++) {
                uint32_t r0, r1, r2, r3;
                ldsm4(r0, r1, r2, r3, bH_base + bt * 16 * PAD_ROW + ko);
                bh[bt * 2 + 0][0] = r0; bh[bt * 2 + 0][1] = r2;
                bh[bt * 2 + 1][0] = r1; bh[bt * 2 + 1][1] = r3;
            }
            #pragma unroll
            for (int mt = 0; mt < 4; mt++) {
                uint32_t aH[4], aL[4];
                ldsm4(aH[0], aH[1], aH[2], aH[3], aH_base + mt * 16 * PAD_ROW + ko);
                ldsm4(aL[0], aL[1], aL[2], aL[3], aL_base + mt * 16 * PAD_ROW + ko);
                #pragma unroll
                for (int ni = 0; ni < 4; ni++) mma16816(c[mt][ni], aH, bh[ni][0], bh[ni][1]);
                #pragma unroll
                for (int ni = 0; ni < 4; ni++) mma16816(c[mt][ni], aL, bh[ni][0], bh[ni][1]);
            }
        }
    }

    // Epilogue
    const int crow0 = m0 + wr * 64 + (lane >> 2);
    const int ccol0 = n0 + wc * 32 + (lane & 3) * 2;
    #pragma unroll
    for (int mt = 0; mt < 4; mt++) {
        #pragma unroll
        for (int ni = 0; ni < 4; ni++) {
            const int cc = ccol0 + ni * 8;
            const float* cf = c[mt][ni];
            const int r0 = crow0 + mt * 16;
            const int r1 = r0 + 8;
            if (epi == 0) {
                float b0 = bias[cc], b1 = bias[cc + 1];
                float2 v0 = { cf[0] + b0, cf[1] + b1 };
                float2 v1 = { cf[2] + b0, cf[3] + b1 };
                *reinterpret_cast<float2*>(C + (size_t)r0 * DIM + cc) = v0;
                *reinterpret_cast<float2*>(C + (size_t)r1 * DIM + cc) = v1;
            } else if (epi == 1) {
                const int h = cc >> 6, d = cc & 63;
                #pragma unroll
                for (int s = 0; s < 2; s++) {
                    const int r = s ? r1 : r0;
                    const int b = r >> 8, q = r & 255;
                    size_t idx = (((size_t)(b * HEADS + h)) * NMM + q) * HD + d;
                    uint32_t hh, ll;
                    pack_hl(cf[s * 2], cf[s * 2 + 1], hh, ll);
                    *reinterpret_cast<uint32_t*>(QhO + idx) = hh;
                    *reinterpret_cast<uint32_t*>(QlO + idx) = ll;
                }
            } else {
                const bool isK = (cc < DIM);
                const int ccl = isK ? cc : cc - DIM;
                const int h = ccl >> 6, d = ccl & 63;
                __half* Hd = isK ? KhO : VhO;
                #pragma unroll
                for (int s = 0; s < 2; s++) {
                    const int r = s ? r1 : r0;
                    const int b = r >> 8, t = r & 255;
                    size_t idx = (((size_t)(b * HEADS + h)) * NKV + t) * HD + d;
                    *reinterpret_cast<uint32_t*>(Hd + idx) = pack_h(cf[s * 2], cf[s * 2 + 1]);
                }
            }
        }
    }
}

// ---------------------------------------------------------------------------
// QK + softmax. CTA: 64 q rows x 256 tokens, 8 warps (2x4), occ 2.
// Stage buffer aliases dead Q/K region. K hi-only; Q 2-term.
// ---------------------------------------------------------------------------
#define QK_PAD 144
#define QK_QH  0
#define QK_QL  (64 * QK_PAD)              // 9216
#define QK_KH  (2 * 64 * QK_PAD)          // 18432 (K: 256 rows -> ends 55296)
#define QK_STG 0                          // aliases Q/K, 64*260*4 = 66560
#define QK_RED 66560                      // pmax/psum: 2*64*4*4 = 2048
#define QK_SMEM (QK_RED + 2048)           // 68608

__global__ __launch_bounds__(256, 2)
void attn_qk_kernel(const __half* __restrict__ Qh, const __half* __restrict__ Ql,
                    const __half* __restrict__ Kh,
                    float* __restrict__ attnF, __half* __restrict__ Ph,
                    int writeAttn) {
    extern __shared__ char smem[];
    const uint32_t sb = smem_u32(smem);
    const int bh = blockIdx.y;
    const int q0 = blockIdx.x * 64;
    const int tid  = threadIdx.x;
    const int lane = tid & 31;
    const int wid  = tid >> 5;
    const int wr = wid >> 2;   // 0..1 -> 32 q rows
    const int wc = wid & 3;    // 0..3 -> 64 tokens

    const __half* gQh = Qh + ((size_t)bh * NMM + q0) * HD;
    const __half* gQl = Ql + ((size_t)bh * NMM + q0) * HD;
    const __half* gKh = Kh + (size_t)bh * NKV * HD;
    for (int idx = tid; idx < 512; idx += 256) {
        int row = idx >> 3, cq = idx & 7;
        cp_async16(sb + QK_QH + row * QK_PAD + cq * 16, gQh + row * HD + cq * 8);
        cp_async16(sb + QK_QL + row * QK_PAD + cq * 16, gQl + row * HD + cq * 8);
    }
    for (int idx = tid; idx < 2048; idx += 256) {
        int row = idx >> 3, cq = idx & 7;
        cp_async16(sb + QK_KH + row * QK_PAD + cq * 16, gKh + row * HD + cq * 8);
    }
    cp_commit();
    cp_wait<0>();
    __syncthreads();

    float c[2][8][4];
    #pragma unroll
    for (int i = 0; i < 2; i++)
        #pragma unroll
        for (int j = 0; j < 8; j++)
            #pragma unroll
            for (int k = 0; k < 4; k++) c[i][j][k] = 0.0f;

    const int lr = lane & 15;
    const int lc16 = (lane >> 4) * 16;

    #pragma unroll
    for (int kk = 0; kk < 4; kk++) {
        const uint32_t ko = kk * 32;
        uint32_t aH[2][4], aL[2][4];
        #pragma unroll
        for (int mt = 0; mt < 2; mt++) {
            const uint32_t ab = sb + QK_QH + (wr * 32 + mt * 16 + lr) * QK_PAD + ko + lc16;
            ldsm4(aH[mt][0], aH[mt][1], aH[mt][2], aH[mt][3], ab);
            ldsm4(aL[mt][0], aL[mt][1], aL[mt][2], aL[mt][3], ab + QK_QL);
        }
        #pragma unroll
        for (int tb = 0; tb < 4; tb++) {
            const uint32_t bb = sb + QK_KH + (wc * 64 + tb * 16 + lr) * QK_PAD + ko + lc16;
            uint32_t h0, h1, h2, h3;
            ldsm4(h0, h1, h2, h3, bb);
            #pragma unroll
            for (int mt = 0; mt < 2; mt++) {
                mma16816(c[mt][tb * 2],     aH[mt], h0, h2);
                mma16816(c[mt][tb * 2],     aL[mt], h0, h2);
                mma16816(c[mt][tb * 2 + 1], aH[mt], h1, h3);
                mma16816(c[mt][tb * 2 + 1], aL[mt], h1, h3);
            }
        }
    }

    float* pmax = reinterpret_cast<float*>(smem + QK_RED);   // [64][4]
    float* psum = pmax + 256;
    const float scale = 0.125f;

    float rowM[2][2];
    #pragma unroll
    for (int mt = 0; mt < 2; mt++) {
        #pragma unroll
        for (int s2 = 0; s2 < 2; s2++) {
            float m = -INFINITY;
            #pragma unroll
            for (int nt = 0; nt < 8; nt++) {
                m = fmaxf(m, c[mt][nt][s2 * 2]);
                m = fmaxf(m, c[mt][nt][s2 * 2 + 1]);
            }
            m = fmaxf(m, __shfl_xor_sync(0xffffffffu, m, 1));
            m = fmaxf(m, __shfl_xor_sync(0xffffffffu, m, 2));
            if ((lane & 3) == 0) {
                int r = wr * 32 + mt * 16 + (lane >> 2) + s2 * 8;
                pmax[r * 4 + wc] = m;
            }
        }
    }
    __syncthreads();
    #pragma unroll
    for (int mt = 0; mt < 2; mt++) {
        #pragma unroll
        for (int s2 = 0; s2 < 2; s2++) {
            int r = wr * 32 + mt * 16 + (lane >> 2) + s2 * 8;
            rowM[mt][s2] = fmaxf(fmaxf(pmax[r * 4], pmax[r * 4 + 1]),
                                 fmaxf(pmax[r * 4 + 2], pmax[r * 4 + 3]));
        }
    }
    #pragma unroll
    for (int mt = 0; mt < 2; mt++) {
        #pragma unroll
        for (int s2 = 0; s2 < 2; s2++) {
            float m = rowM[mt][s2];
            float sum = 0.0f;
            #pragma unroll
            for (int nt = 0; nt < 8; nt++) {
                float e0 = __expf((c[mt][nt][s2 * 2]     - m) * scale);
                float e1 = __expf((c[mt][nt][s2 * 2 + 1] - m) * scale);
                c[mt][nt][s2 * 2]     = e0;
                c[mt][nt][s2 * 2 + 1] = e1;
                sum += e0 + e1;
            }
            sum += __shfl_xor_sync(0xffffffffu, sum, 1);
            sum += __shfl_xor_sync(0xffffffffu, sum, 2);
            if ((lane & 3) == 0) {
                int r = wr * 32 + mt * 16 + (lane >> 2) + s2 * 8;
                psum[r * 4 + wc] = sum;
            }
        }
    }
    __syncthreads();
    #pragma unroll
    for (int mt = 0; mt < 2; mt++) {
        #pragma unroll
        for (int s2 = 0; s2 < 2; s2++) {
            int r = wr * 32 + mt * 16 + (lane >> 2) + s2 * 8;
            float S = psum[r * 4] + psum[r * 4 + 1] + psum[r * 4 + 2] + psum[r * 4 + 3];
            float inv = 1.0f / S;
            #pragma unroll
            for (int nt = 0; nt < 8; nt++) {
                c[mt][nt][s2 * 2]     *= inv;
                c[mt][nt][s2 * 2 + 1] *= inv;
            }
        }
    }

    // Stage to smem (aliases dead Q/K region; both prior syncthreads guarantee
    // all ldmatrix reads of Q/K completed), then coalesced global writes.
    float* stg = reinterpret_cast<float*>(smem + QK_STG);    // [64][260]
    #pragma unroll
    for (int mt = 0; mt < 2; mt++) {
        #pragma unroll
        for (int nt = 0; nt < 8; nt++) {
            int rl = wr * 32 + mt * 16 + (lane >> 2);
            int col = wc * 64 + nt * 8 + (lane & 3) * 2;
            stg[rl * 260 + col]           = c[mt][nt][0];
            stg[rl * 260 + col + 1]       = c[mt][nt][1];
            stg[(rl + 8) * 260 + col]     = c[mt][nt][2];
            stg[(rl + 8) * 260 + col + 1] = c[mt][nt][3];
        }
    }
    __syncthreads();
    for (int idx = tid; idx < 4096; idx += 256) {
        int r = idx >> 6, c4 = (idx & 63) * 4;
        float4 v = *reinterpret_cast<float4*>(&stg[r * 260 + c4]);
        size_t base = ((size_t)bh * NMM + q0 + r) * NKV + c4;
        if (writeAttn)
            *reinterpret_cast<float4*>(attnF + base) = v;
        uint2 hv = { pack_h(v.x, v.y), pack_h(v.z, v.w) };
        *reinterpret_cast<uint2*>(Ph + base) = hv;
    }
}

// ---------------------------------------------------------------------------
// AV kernel (1-term fp16): O = P @ V. 128 rows/CTA, 3-stage pipeline.
// ---------------------------------------------------------------------------
#define AV_APAD 80
#define AV_VPAD 144
#define AV_A 0
#define AV_V (128 * AV_APAD)               // 10240
#define AV_STAGE (AV_V + 32 * AV_VPAD)     // 14848
#define AV_SMEM (3 * AV_STAGE)             // 44544

__global__ __launch_bounds__(256, 2)
void av_kernel(const __half* __restrict__ Ph, const __half* __restrict__ Vh,
               __half* __restrict__ Oh, __half* __restrict__ Ol) {
    extern __shared__ char smem[];
    const uint32_t sb = smem_u32(smem);
    const int bh = blockIdx.y;
    const int m0 = blockIdx.x * 128;
    const int b = bh / HEADS, h = bh % HEADS;
    const int tid  = threadIdx.x;
    const int lane = tid & 31;
    const int wid  = tid >> 5;
    const int wr = wid >> 2;
    const int wc = wid & 3;

    const __half* gA = Ph + ((size_t)bh * NMM + m0) * NKV;
    const __half* gV = Vh + (size_t)bh * NKV * HD;

    auto issue_stage = [&](int ck, int s) {
        const int k0 = ck * 32;
        const uint32_t sbase = sb + s * AV_STAGE;
        #pragma unroll
        for (int t = 0; t < 2; t++) {
            int idx = tid + t * 256;
            int row = idx >> 2, cq = idx & 3;
            cp_async16(sbase + AV_A + row * AV_APAD + cq * 16, gA + (size_t)row * NKV + k0 + cq * 8);
        }
        {
            int row = tid >> 3, cq = tid & 7;
            cp_async16(sbase + AV_V + row * AV_VPAD + cq * 16, gV + (size_t)(k0 + row) * HD + cq * 8);
        }
        cp_commit();
    };

    float c[4][2][4];
    #pragma unroll
    for (int i = 0; i < 4; i++)
        #pragma unroll
        for (int j = 0; j < 2; j++)
            #pragma unroll
            for (int k = 0; k < 4; k++) c[i][j][k] = 0.0f;

    const int lr = lane & 15;
    const int lc16 = (lane >> 4) * 16;

    issue_stage(0, 0);
    issue_stage(1, 1);

    const int nchunks = NKV / 32;  // 8
    for (int i = 0; i < nchunks; i++) {
        if (i + 1 < nchunks) cp_wait<1>(); else cp_wait<0>();
        __syncthreads();
        if (i + 2 < nchunks) issue_stage(i + 2, (i + 2) % 3);

        const uint32_t st = sb + (i % 3) * AV_STAGE;
        #pragma unroll
        for (int kk = 0; kk < 2; kk++) {
            const uint32_t ko = kk * 32;
            uint32_t vh0, vh1, vh2, vh3;
            const uint32_t vb = st + AV_V + (kk * 16 + lr) * AV_VPAD + wc * 32 + lc16;
            ldsm4t(vh0, vh1, vh2, vh3, vb);
            #pragma unroll
            for (int mt = 0; mt < 4; mt++) {
                uint32_t a[4];
                const uint32_t ab = st + AV_A + (wr * 64 + mt * 16 + lr) * AV_APAD + ko + lc16;
                ldsm4(a[0], a[1], a[2], a[3], ab);
                mma16816(c[mt][0], a, vh0, vh1);
                mma16816(c[mt][1], a, vh2, vh3);
            }
        }
    }

    #pragma unroll
    for (int mt = 0; mt < 4; mt++) {
        #pragma unroll
        for (int nt = 0; nt < 2; nt++) {
            const int d = wc * 16 + nt * 8 + (lane & 3) * 2;
            #pragma unroll
            for (int s = 0; s < 2; s++) {
                const int q = m0 + wr * 64 + mt * 16 + (lane >> 2) + s * 8;
                size_t idx = ((size_t)(b * NMM + q)) * DIM + h * HD + d;
                uint32_t hh, ll;
                pack_hl(c[mt][nt][s * 2], c[mt][nt][s * 2 + 1], hh, ll);
                *reinterpret_cast<uint32_t*>(Oh + idx) = hh;
                *reinterpret_cast<uint32_t*>(Ol + idx) = ll;
            }
        }
    }
}

// ---------------------------------------------------------------------------
// Launch
// ---------------------------------------------------------------------------
extern "C" void kernel_launch(void* const* d_in, const int* in_sizes, int n_in,
                              void* d_out, int out_size) {
    const float* xmm   = (const float*)d_in[0];
    const float* xv    = (const float*)d_in[1];
    const float* xa    = (const float*)d_in[2];
    const float* Wq    = (const float*)d_in[3];
    const float* Wkv   = (const float*)d_in[4];
    const float* Wproj = (const float*)d_in[5];
    const float* bproj = (const float*)d_in[6];
    float* out = (float*)d_out;

    __half *xmm_h, *xmm_l, *xsrc_h, *xsrc_l;
    __half *WqT_h, *WkvT_h, *WpT_h;
    __half *Qh, *Ql, *Kh, *Vh, *Ph, *Oh, *Ol;
    float* attn_fb;
    cudaGetSymbolAddress((void**)&xmm_h,  g_xmm_h);
    cudaGetSymbolAddress((void**)&xmm_l,  g_xmm_l);
    cudaGetSymbolAddress((void**)&xsrc_h, g_xsrc_h);
    cudaGetSymbolAddress((void**)&xsrc_l, g_xsrc_l);
    cudaGetSymbolAddress((void**)&WqT_h,  g_WqT_h);
    cudaGetSymbolAddress((void**)&WkvT_h, g_WkvT_h);
    cudaGetSymbolAddress((void**)&WpT_h,  g_WpT_h);
    cudaGetSymbolAddress((void**)&Qh,  g_Qh);
    cudaGetSymbolAddress((void**)&Ql,  g_Ql);
    cudaGetSymbolAddress((void**)&Kh,  g_Kh);
    cudaGetSymbolAddress((void**)&Vh,  g_Vh);
    cudaGetSymbolAddress((void**)&Ph,  g_Ph);
    cudaGetSymbolAddress((void**)&Oh,  g_Oh);
    cudaGetSymbolAddress((void**)&Ol,  g_Ol);
    cudaGetSymbolAddress((void**)&attn_fb, g_attn_fallback);

    const int writeAttn = (out_size >= (OUT_ELEMS + ATTN_ELEMS)) ? 1 : 0;
    float* attn = writeAttn ? (out + OUT_ELEMS) : attn_fb;

    cudaFuncSetAttribute(proj_kernel, cudaFuncAttributeMaxDynamicSharedMemorySize, GEMM_SMEM);
    cudaFuncSetAttribute(attn_qk_kernel, cudaFuncAttributeMaxDynamicSharedMemorySize, QK_SMEM);
    cudaFuncSetAttribute(av_kernel, cudaFuncAttributeMaxDynamicSharedMemorySize, AV_SMEM);

    // 1) split inputs (xmm + gathered xsrc) in one launch
    prep_inputs_kernel<<<2 * N4 / 256, 256>>>(
        (const float4*)xmm, xv, xa,
        (uint2*)xmm_h, (uint2*)xmm_l, (uint2*)xsrc_h, (uint2*)xsrc_l);

    // 2) weight transposes
    {
        dim3 blk(32, 8);
        transpose_h_kernel<<<dim3(DIM / 32, DIM / 32),   blk>>>(Wq,    WqT_h,  DIM, DIM);
        transpose_h_kernel<<<dim3(KVDIM / 32, DIM / 32), blk>>>(Wkv,   WkvT_h, DIM, KVDIM);
        transpose_h_kernel<<<dim3(DIM / 32, DIM / 32),   blk>>>(Wproj, WpT_h,  DIM, DIM);
    }

    // 3) merged Q + KV projections (one launch)
    proj_kernel<<<dim3(18, M_ROWS / 128), 256, GEMM_SMEM>>>(
        1, xmm_h, xmm_l, WqT_h, xsrc_h, xsrc_l, WkvT_h,
        nullptr, nullptr, Qh, Ql, Kh, Vh);

    // 4) QK + softmax -> attn (optional) + P fp16
    attn_qk_kernel<<<dim3(NMM / 64, NBH), 256, QK_SMEM>>>(
        Qh, Ql, Kh, attn, Ph, writeAttn);

    // 5) AV -> O hi/lo
    av_kernel<<<dim3(NMM / 128, NBH), 256, AV_SMEM>>>(Ph, Vh, Oh, Ol);

    // 6) out-proj
    proj_kernel<<<dim3(6, M_ROWS / 128), 256, GEMM_SMEM>>>(
        0, Oh, Ol, WpT_h, nullptr, nullptr, nullptr,
        bproj, out, nullptr, nullptr, nullptr, nullptr);
}

// round 8
// speedup vs baseline: 3.7645x; 1.0976x over previous
#include <cuda_runtime.h>
#include <cuda_fp16.h>
#include <math.h>
#include <stdint.h>

#define BS    32
#define NMM   256
#define NV    196
#define NA    60
#define NKV   256
#define DIM   768
#define HEADS 12
#define HD    64
#define KVDIM 1536

#define OUT_ELEMS  (BS * NMM * DIM)
#define ATTN_ELEMS (BS * HEADS * NMM * NKV)
#define M_ROWS     (BS * NMM)
#define NBH        (BS * HEADS)

// ---------------------------------------------------------------------------
// Scratch
// ---------------------------------------------------------------------------
__device__ __half g_xmm_h[M_ROWS * DIM];
__device__ __half g_xmm_l[M_ROWS * DIM];
__device__ __half g_xsrc_h[M_ROWS * DIM];
__device__ __half g_xsrc_l[M_ROWS * DIM];
__device__ __half g_WqT_h[DIM * DIM];
__device__ __half g_WkvT_h[KVDIM * DIM];
__device__ __half g_WpT_h[DIM * DIM];

__device__ __half g_Qh[NBH * NMM * HD];
__device__ __half g_Ql[NBH * NMM * HD];
__device__ __half g_Kh[NBH * NKV * HD];
__device__ __half g_Vh[NBH * NKV * HD];
__device__ __half g_Oh[M_ROWS * DIM];
__device__ float g_attn_fallback[ATTN_ELEMS];

// ---------------------------------------------------------------------------
// PTX helpers
// ---------------------------------------------------------------------------
__device__ __forceinline__ uint32_t smem_u32(const void* p) {
    uint32_t a;
    asm("{ .reg .u64 t; cvta.to.shared.u64 t, %1; cvt.u32.u64 %0, t; }" : "=r"(a) : "l"(p));
    return a;
}
__device__ __forceinline__ void cp_async16(uint32_t sa, const void* gp) {
    asm volatile("cp.async.cg.shared.global [%0], [%1], 16;" :: "r"(sa), "l"(gp) : "memory");
}
__device__ __forceinline__ void cp_commit() {
    asm volatile("cp.async.commit_group;" ::: "memory");
}
template <int N>
__device__ __forceinline__ void cp_wait() {
    asm volatile("cp.async.wait_group %0;" :: "n"(N) : "memory");
}
__device__ __forceinline__ void ldsm4(uint32_t& r0, uint32_t& r1, uint32_t& r2, uint32_t& r3,
                                      uint32_t addr) {
    asm volatile("ldmatrix.sync.aligned.m8n8.x4.shared.b16 {%0,%1,%2,%3}, [%4];"
                 : "=r"(r0), "=r"(r1), "=r"(r2), "=r"(r3) : "r"(addr));
}
__device__ __forceinline__ void ldsm4t(uint32_t& r0, uint32_t& r1, uint32_t& r2, uint32_t& r3,
                                       uint32_t addr) {
    asm volatile("ldmatrix.sync.aligned.m8n8.x4.trans.shared.b16 {%0,%1,%2,%3}, [%4];"
                 : "=r"(r0), "=r"(r1), "=r"(r2), "=r"(r3) : "r"(addr));
}
__device__ __forceinline__ void mma16816(float* c, const uint32_t* a, uint32_t b0, uint32_t b1) {
    asm volatile(
        "mma.sync.aligned.m16n8k16.row.col.f32.f16.f16.f32 "
        "{%0,%1,%2,%3}, {%4,%5,%6,%7}, {%8,%9}, {%0,%1,%2,%3};"
        : "+f"(c[0]), "+f"(c[1]), "+f"(c[2]), "+f"(c[3])
        : "r"(a[0]), "r"(a[1]), "r"(a[2]), "r"(a[3]), "r"(b0), "r"(b1));
}

__device__ __forceinline__ void pack_hl(float f0, float f1, uint32_t& h, uint32_t& l) {
    __half h0 = __float2half_rn(f0);
    __half h1 = __float2half_rn(f1);
    __half l0 = __float2half_rn(f0 - __half2float(h0));
    __half l1 = __float2half_rn(f1 - __half2float(h1));
    __half2 hp = __halves2half2(h0, h1);
    __half2 lp = __halves2half2(l0, l1);
    h = *reinterpret_cast<uint32_t*>(&hp);
    l = *reinterpret_cast<uint32_t*>(&lp);
}
__device__ __forceinline__ uint32_t pack_h(float f0, float f1) {
    __half2 hp = __halves2half2(__float2half_rn(f0), __float2half_rn(f1));
    return *reinterpret_cast<uint32_t*>(&hp);
}

// ---------------------------------------------------------------------------
// Input conversion
// ---------------------------------------------------------------------------
__device__ __forceinline__ void split4(float4 v, uint2& hv, uint2& lv) {
    uint32_t h0, l0, h1, l1;
    pack_hl(v.x, v.y, h0, l0);
    pack_hl(v.z, v.w, h1, l1);
    hv.x = h0; hv.y = h1; lv.x = l0; lv.y = l1;
}

#define N4 (M_ROWS * DIM / 4)

__global__ __launch_bounds__(256)
void prep_inputs_kernel(const float4* __restrict__ xmm,
                        const float* __restrict__ xv, const float* __restrict__ xa,
                        uint2* __restrict__ xmm_h, uint2* __restrict__ xmm_l,
                        uint2* __restrict__ xsrc_h, uint2* __restrict__ xsrc_l) {
    int i = blockIdx.x * 256 + threadIdx.x;
    if (i < N4) {
        uint2 hv, lv;
        split4(xmm[i], hv, lv);
        xmm_h[i] = hv;
        xmm_l[i] = lv;
    } else {
        i -= N4;
        const int C4 = DIM / 4;
        int row = i / C4;
        int c4  = i - row * C4;
        int b = row >> 8;
        int r = row & 255;
        const float4* src = (r < NV)
            ? reinterpret_cast<const float4*>(xv + (size_t)(b * NV + r) * DIM)
            : reinterpret_cast<const float4*>(xa + (size_t)(b * NA + (r - NV)) * DIM);
        uint2 hv, lv;
        split4(src[c4], hv, lv);
        xsrc_h[i] = hv;
        xsrc_l[i] = lv;
    }
}

// All 3 weight transposes in one launch. grid (96, 24), block (32, 8).
__global__ __launch_bounds__(256)
void transpose_all_kernel(const float* __restrict__ Wq, const float* __restrict__ Wkv,
                          const float* __restrict__ Wp,
                          __half* __restrict__ WqT, __half* __restrict__ WkvT,
                          __half* __restrict__ WpT) {
    __shared__ float t[32][33];
    int bx = blockIdx.x;
    const float* W; __half* T; int N; int nb;
    if (bx < 24)      { W = Wq;  T = WqT;  N = DIM;   nb = bx; }
    else if (bx < 72) { W = Wkv; T = WkvT; N = KVDIM; nb = bx - 24; }
    else              { W = Wp;  T = WpT;  N = DIM;   nb = bx - 72; }
    int k0 = blockIdx.y * 32, n0 = nb * 32;
    int x = threadIdx.x, y = threadIdx.y;
    #pragma unroll
    for (int i = 0; i < 32; i += 8)
        t[y + i][x] = W[(size_t)(k0 + y + i) * N + n0 + x];
    __syncthreads();
    #pragma unroll
    for (int i = 0; i < 32; i += 8)
        T[(size_t)(n0 + y + i) * DIM + k0 + x] = __float2half_rn(t[x][y + i]);
}

// ---------------------------------------------------------------------------
// fp16 HMMA GEMM, runtime epilogue select.
// mode 0: out-proj (1-term A, bias, fp32 C). mode 1: merged Q+KV projection
//   (2-term A; blockIdx.x < 6 -> Q epi; else KV epi).
// ---------------------------------------------------------------------------
#define GK 768
#define PAD_ROW 80
#define ARR_BYTES (128 * PAD_ROW)
#define STAGE_BYTES (3 * ARR_BYTES)
#define GEMM_SMEM (3 * STAGE_BYTES)

__global__ __launch_bounds__(256, 2)
void proj_kernel(int mode,
                 const __half* __restrict__ A0h, const __half* __restrict__ A0l,
                 const __half* __restrict__ B0T,
                 const __half* __restrict__ A1h, const __half* __restrict__ A1l,
                 const __half* __restrict__ B1T,
                 const float* __restrict__ bias, float* __restrict__ C,
                 __half* __restrict__ QhO, __half* __restrict__ QlO,
                 __half* __restrict__ KhO, __half* __restrict__ VhO) {
    extern __shared__ char smem[];
    const uint32_t sb = smem_u32(smem);

    const int tid  = threadIdx.x;
    const int lane = tid & 31;
    const int wid  = tid >> 5;
    const int wr   = wid >> 2;
    const int wc   = wid & 3;
    const int m0   = blockIdx.y * 128;
    const int twoTerm = (mode != 0);

    int epi, n0;
    const __half *Ahp, *Alp, *BTp;
    if (mode == 0) {
        epi = 0; Ahp = A0h; Alp = A0l; BTp = B0T; n0 = blockIdx.x * 128;
    } else if (blockIdx.x < 6) {
        epi = 1; Ahp = A0h; Alp = A0l; BTp = B0T; n0 = blockIdx.x * 128;
    } else {
        epi = 2; Ahp = A1h; Alp = A1l; BTp = B1T; n0 = (blockIdx.x - 6) * 128;
    }

    const __half* base0 = Ahp + (size_t)m0 * GK;
    const __half* base1 = Alp + (size_t)m0 * GK;
    const __half* base2 = BTp + (size_t)n0 * GK;

    auto issue_stage = [&](int chunk, int s) {
        const int k0 = chunk << 5;
        const uint32_t sbase = sb + s * STAGE_BYTES;
        #pragma unroll
        for (int it = 0; it < 6; it++) {
            const int arr = it >> 1;
            if (arr == 1 && !twoTerm) continue;
            const int j   = tid + (it & 1) * 256;
            const int row = j >> 2;
            const int q   = j & 3;
            const __half* gp =
                (arr == 0 ? base0 : arr == 1 ? base1 : base2)
                + (size_t)row * GK + k0 + q * 8;
            cp_async16(sbase + arr * ARR_BYTES + row * PAD_ROW + q * 16, gp);
        }
        cp_commit();
    };

    float c[4][4][4];
    #pragma unroll
    for (int i = 0; i < 4; i++)
        #pragma unroll
        for (int j = 0; j < 4; j++)
            #pragma unroll
            for (int k = 0; k < 4; k++) c[i][j][k] = 0.0f;

    const int lr   = lane & 15;
    const int lc16 = (lane >> 4) * 16;

    issue_stage(0, 0);
    issue_stage(1, 1);

    const int nchunks = GK / 32;  // 24
    for (int i = 0; i < nchunks; i++) {
        if (i + 1 < nchunks) cp_wait<1>(); else cp_wait<0>();
        __syncthreads();
        if (i + 2 < nchunks) issue_stage(i + 2, (i + 2) % 3);

        const uint32_t st = sb + (i % 3) * STAGE_BYTES;
        const uint32_t aH_base = st + 0 * ARR_BYTES + (wr * 64 + lr) * PAD_ROW + lc16;
        const uint32_t aL_base = st + 1 * ARR_BYTES + (wr * 64 + lr) * PAD_ROW + lc16;
        const uint32_t bH_base = st + 2 * ARR_BYTES + (wc * 32 + lr) * PAD_ROW + lc16;

        #pragma unroll
        for (int kk = 0; kk < 2; kk++) {
            const uint32_t ko = kk * 32;
            uint32_t bh[4][2];
            #pragma unroll
            for (int bt = 0; bt < 2; bt++) {
                uint32_t r0, r1, r2, r3;
                ldsm4(r0, r1, r2, r3, bH_base + bt * 16 * PAD_ROW + ko);
                bh[bt * 2 + 0][0] = r0; bh[bt * 2 + 0][1] = r2;
                bh[bt * 2 + 1][0] = r1; bh[bt * 2 + 1][1] = r3;
            }
            #pragma unroll
            for (int mt = 0; mt < 4; mt++) {
                uint32_t aH[4], aL[4];
                ldsm4(aH[0], aH[1], aH[2], aH[3], aH_base + mt * 16 * PAD_ROW + ko);
                if (twoTerm)
                    ldsm4(aL[0], aL[1], aL[2], aL[3], aL_base + mt * 16 * PAD_ROW + ko);
                #pragma unroll
                for (int ni = 0; ni < 4; ni++) mma16816(c[mt][ni], aH, bh[ni][0], bh[ni][1]);
                if (twoTerm) {
                    #pragma unroll
                    for (int ni = 0; ni < 4; ni++) mma16816(c[mt][ni], aL, bh[ni][0], bh[ni][1]);
                }
            }
        }
    }

    // Epilogue
    const int crow0 = m0 + wr * 64 + (lane >> 2);
    const int ccol0 = n0 + wc * 32 + (lane & 3) * 2;
    #pragma unroll
    for (int mt = 0; mt < 4; mt++) {
        #pragma unroll
        for (int ni = 0; ni < 4; ni++) {
            const int cc = ccol0 + ni * 8;
            const float* cf = c[mt][ni];
            const int r0 = crow0 + mt * 16;
            const int r1 = r0 + 8;
            if (epi == 0) {
                float b0 = bias[cc], b1 = bias[cc + 1];
                float2 v0 = { cf[0] + b0, cf[1] + b1 };
                float2 v1 = { cf[2] + b0, cf[3] + b1 };
                *reinterpret_cast<float2*>(C + (size_t)r0 * DIM + cc) = v0;
                *reinterpret_cast<float2*>(C + (size_t)r1 * DIM + cc) = v1;
            } else if (epi == 1) {
                const int h = cc >> 6, d = cc & 63;
                #pragma unroll
                for (int s = 0; s < 2; s++) {
                    const int r = s ? r1 : r0;
                    const int b = r >> 8, q = r & 255;
                    size_t idx = (((size_t)(b * HEADS + h)) * NMM + q) * HD + d;
                    uint32_t hh, ll;
                    pack_hl(cf[s * 2], cf[s * 2 + 1], hh, ll);
                    *reinterpret_cast<uint32_t*>(QhO + idx) = hh;
                    *reinterpret_cast<uint32_t*>(QlO + idx) = ll;
                }
            } else {
                const bool isK = (cc < DIM);
                const int ccl = isK ? cc : cc - DIM;
                const int h = ccl >> 6, d = ccl & 63;
                __half* Hd = isK ? KhO : VhO;
                #pragma unroll
                for (int s = 0; s < 2; s++) {
                    const int r = s ? r1 : r0;
                    const int b = r >> 8, t = r & 255;
                    size_t idx = (((size_t)(b * HEADS + h)) * NKV + t) * HD + d;
                    *reinterpret_cast<uint32_t*>(Hd + idx) = pack_h(cf[s * 2], cf[s * 2 + 1]);
                }
            }
        }
    }
}

// ---------------------------------------------------------------------------
// Fused attention: QK + softmax + attn write + AV, one kernel.
// CTA: 128 q rows of one (b,h). 8 warps, each warp owns 16 q rows x ALL 256
// tokens -> warp-local softmax, P stays in registers (C-frag == A-frag layout).
// ---------------------------------------------------------------------------
#define FA_PAD 144
#define FA_QH 0
#define FA_QL (128 * FA_PAD)              // 18432
#define FA_K  (2 * 128 * FA_PAD)          // 36864
#define FA_V  (FA_K + 256 * FA_PAD)       // 73728
#define FA_SMEM (FA_V + 256 * FA_PAD)     // 110592

__global__ __launch_bounds__(256, 1)
void fused_attn_kernel(const __half* __restrict__ Qh, const __half* __restrict__ Ql,
                       const __half* __restrict__ Kh, const __half* __restrict__ Vh,
                       float* __restrict__ attnF, __half* __restrict__ Oh,
                       int writeAttn) {
    extern __shared__ char smem[];
    const uint32_t sb = smem_u32(smem);
    const int bh = blockIdx.y;
    const int q0 = blockIdx.x * 128;
    const int tid  = threadIdx.x;
    const int lane = tid & 31;
    const int wid  = tid >> 5;

    const __half* gQh = Qh + ((size_t)bh * NMM + q0) * HD;
    const __half* gQl = Ql + ((size_t)bh * NMM + q0) * HD;
    const __half* gKh = Kh + (size_t)bh * NKV * HD;
    const __half* gVh = Vh + (size_t)bh * NKV * HD;

    for (int idx = tid; idx < 1024; idx += 256) {
        int row = idx >> 3, cq = idx & 7;
        cp_async16(sb + FA_QH + row * FA_PAD + cq * 16, gQh + row * HD + cq * 8);
        cp_async16(sb + FA_QL + row * FA_PAD + cq * 16, gQl + row * HD + cq * 8);
    }
    for (int idx = tid; idx < 2048; idx += 256) {
        int row = idx >> 3, cq = idx & 7;
        cp_async16(sb + FA_K + row * FA_PAD + cq * 16, gKh + row * HD + cq * 8);
        cp_async16(sb + FA_V + row * FA_PAD + cq * 16, gVh + row * HD + cq * 8);
    }
    cp_commit();
    cp_wait<0>();
    __syncthreads();

    const int lr = lane & 15;
    const int lc16 = (lane >> 4) * 16;
    const int rowbase = wid * 16;

    // ---- QK: S[16 x 256], c[nt] covers tokens [8nt, 8nt+8) ----
    float c[32][4];
    #pragma unroll
    for (int j = 0; j < 32; j++)
        #pragma unroll
        for (int k = 0; k < 4; k++) c[j][k] = 0.0f;

    #pragma unroll
    for (int kk = 0; kk < 4; kk++) {
        const uint32_t ko = kk * 32;
        uint32_t aH[4], aL[4];
        const uint32_t ab = sb + FA_QH + (rowbase + lr) * FA_PAD + ko + lc16;
        ldsm4(aH[0], aH[1], aH[2], aH[3], ab);
        ldsm4(aL[0], aL[1], aL[2], aL[3], ab + FA_QL);
        #pragma unroll
        for (int tb = 0; tb < 16; tb++) {
            const uint32_t bb = sb + FA_K + (tb * 16 + lr) * FA_PAD + ko + lc16;
            uint32_t h0, h1, h2, h3;
            ldsm4(h0, h1, h2, h3, bb);
            mma16816(c[tb * 2],     aH, h0, h2);
            mma16816(c[tb * 2],     aL, h0, h2);
            mma16816(c[tb * 2 + 1], aH, h1, h3);
            mma16816(c[tb * 2 + 1], aL, h1, h3);
        }
    }

    // ---- warp-local softmax over 256 tokens (rows r=lane>>2 and r+8) ----
    const float scale = 0.125f;
    #pragma unroll
    for (int s2 = 0; s2 < 2; s2++) {
        float m = -INFINITY;
        #pragma unroll
        for (int nt = 0; nt < 32; nt++) {
            m = fmaxf(m, c[nt][s2 * 2]);
            m = fmaxf(m, c[nt][s2 * 2 + 1]);
        }
        m = fmaxf(m, __shfl_xor_sync(0xffffffffu, m, 1));
        m = fmaxf(m, __shfl_xor_sync(0xffffffffu, m, 2));
        float sum = 0.0f;
        #pragma unroll
        for (int nt = 0; nt < 32; nt++) {
            float e0 = __expf((c[nt][s2 * 2]     - m) * scale);
            float e1 = __expf((c[nt][s2 * 2 + 1] - m) * scale);
            c[nt][s2 * 2]     = e0;
            c[nt][s2 * 2 + 1] = e1;
            sum += e0 + e1;
        }
        sum += __shfl_xor_sync(0xffffffffu, sum, 1);
        sum += __shfl_xor_sync(0xffffffffu, sum, 2);
        float inv = 1.0f / sum;
        #pragma unroll
        for (int nt = 0; nt < 32; nt++) {
            c[nt][s2 * 2]     *= inv;
            c[nt][s2 * 2 + 1] *= inv;
        }
    }

    // ---- write attn (fp32) straight from fragments ----
    if (writeAttn) {
        const int r  = lane >> 2;
        const int c0 = (lane & 3) * 2;
        float* rowp0 = attnF + ((size_t)bh * NMM + q0 + rowbase + r)     * NKV + c0;
        float* rowp1 = attnF + ((size_t)bh * NMM + q0 + rowbase + r + 8) * NKV + c0;
        #pragma unroll
        for (int nt = 0; nt < 32; nt++) {
            float2 v0 = { c[nt][0], c[nt][1] };
            float2 v1 = { c[nt][2], c[nt][3] };
            *reinterpret_cast<float2*>(rowp0 + nt * 8) = v0;
            *reinterpret_cast<float2*>(rowp1 + nt * 8) = v1;
        }
    }

    // ---- AV: O[16 x 64] = P @ V, P fragments packed from c in-place ----
    float o[8][4];
    #pragma unroll
    for (int j = 0; j < 8; j++)
        #pragma unroll
        for (int k = 0; k < 4; k++) o[j][k] = 0.0f;

    #pragma unroll
    for (int kt = 0; kt < 16; kt++) {
        uint32_t a[4];
        a[0] = pack_h(c[2 * kt][0],     c[2 * kt][1]);
        a[1] = pack_h(c[2 * kt][2],     c[2 * kt][3]);
        a[2] = pack_h(c[2 * kt + 1][0], c[2 * kt + 1][1]);
        a[3] = pack_h(c[2 * kt + 1][2], c[2 * kt + 1][3]);
        #pragma unroll
        for (int dblk = 0; dblk < 4; dblk++) {
            uint32_t v0, v1, v2, v3;
            const uint32_t vb = sb + FA_V + (kt * 16 + lr) * FA_PAD + dblk * 32 + lc16;
            ldsm4t(v0, v1, v2, v3, vb);
            mma16816(o[dblk * 2],     a, v0, v1);
            mma16816(o[dblk * 2 + 1], a, v2, v3);
        }
    }

    // ---- epilogue: O hi (fp16) -> [b*256+q][h*64+d] ----
    const int b = bh / HEADS, h = bh % HEADS;
    const int r = lane >> 2;
    #pragma unroll
    for (int j = 0; j < 8; j++) {
        const int d = j * 8 + (lane & 3) * 2;
        #pragma unroll
        for (int s = 0; s < 2; s++) {
            const int q = q0 + rowbase + r + s * 8;
            size_t idx = ((size_t)(b * NMM + q)) * DIM + h * HD + d;
            *reinterpret_cast<uint32_t*>(Oh + idx) = pack_h(o[j][s * 2], o[j][s * 2 + 1]);
        }
    }
}

// ---------------------------------------------------------------------------
// Launch
// ---------------------------------------------------------------------------
extern "C" void kernel_launch(void* const* d_in, const int* in_sizes, int n_in,
                              void* d_out, int out_size) {
    const float* xmm   = (const float*)d_in[0];
    const float* xv    = (const float*)d_in[1];
    const float* xa    = (const float*)d_in[2];
    const float* Wq    = (const float*)d_in[3];
    const float* Wkv   = (const float*)d_in[4];
    const float* Wproj = (const float*)d_in[5];
    const float* bproj = (const float*)d_in[6];
    float* out = (float*)d_out;

    __half *xmm_h, *xmm_l, *xsrc_h, *xsrc_l;
    __half *WqT_h, *WkvT_h, *WpT_h;
    __half *Qh, *Ql, *Kh, *Vh, *Oh;
    float* attn_fb;
    cudaGetSymbolAddress((void**)&xmm_h,  g_xmm_h);
    cudaGetSymbolAddress((void**)&xmm_l,  g_xmm_l);
    cudaGetSymbolAddress((void**)&xsrc_h, g_xsrc_h);
    cudaGetSymbolAddress((void**)&xsrc_l, g_xsrc_l);
    cudaGetSymbolAddress((void**)&WqT_h,  g_WqT_h);
    cudaGetSymbolAddress((void**)&WkvT_h, g_WkvT_h);
    cudaGetSymbolAddress((void**)&WpT_h,  g_WpT_h);
    cudaGetSymbolAddress((void**)&Qh,  g_Qh);
    cudaGetSymbolAddress((void**)&Ql,  g_Ql);
    cudaGetSymbolAddress((void**)&Kh,  g_Kh);
    cudaGetSymbolAddress((void**)&Vh,  g_Vh);
    cudaGetSymbolAddress((void**)&Oh,  g_Oh);
    cudaGetSymbolAddress((void**)&attn_fb, g_attn_fallback);

    const int writeAttn = (out_size >= (OUT_ELEMS + ATTN_ELEMS)) ? 1 : 0;
    float* attn = writeAttn ? (out + OUT_ELEMS) : attn_fb;

    cudaFuncSetAttribute(proj_kernel, cudaFuncAttributeMaxDynamicSharedMemorySize, GEMM_SMEM);
    cudaFuncSetAttribute(fused_attn_kernel, cudaFuncAttributeMaxDynamicSharedMemorySize, FA_SMEM);

    // 1) split inputs
    prep_inputs_kernel<<<2 * N4 / 256, 256>>>(
        (const float4*)xmm, xv, xa,
        (uint2*)xmm_h, (uint2*)xmm_l, (uint2*)xsrc_h, (uint2*)xsrc_l);

    // 2) all weight transposes, one launch
    transpose_all_kernel<<<dim3(96, 24), dim3(32, 8)>>>(
        Wq, Wkv, Wproj, WqT_h, WkvT_h, WpT_h);

    // 3) merged Q + KV projections
    proj_kernel<<<dim3(18, M_ROWS / 128), 256, GEMM_SMEM>>>(
        1, xmm_h, xmm_l, WqT_h, xsrc_h, xsrc_l, WkvT_h,
        nullptr, nullptr, Qh, Ql, Kh, Vh);

    // 4) fused QK + softmax + attn write + AV
    fused_attn_kernel<<<dim3(NMM / 128, NBH), 256, FA_SMEM>>>(
        Qh, Ql, Kh, Vh, attn, Oh, writeAttn);

    // 5) out-proj (1-term A)
    proj_kernel<<<dim3(6, M_ROWS / 128), 256, GEMM_SMEM>>>(
        0, Oh, Oh, WpT_h, nullptr, nullptr, nullptr,
        bproj, out, nullptr, nullptr, nullptr, nullptr);
}

// round 9
// speedup vs baseline: 3.9431x; 1.0474x over previous
#include <cuda_runtime.h>
#include <cuda_fp16.h>
#include <math.h>
#include <stdint.h>

#define BS    32
#define NMM   256
#define NV    196
#define NA    60
#define NKV   256
#define DIM   768
#define HEADS 12
#define HD    64
#define KVDIM 1536

#define OUT_ELEMS  (BS * NMM * DIM)
#define ATTN_ELEMS (BS * HEADS * NMM * NKV)
#define M_ROWS     (BS * NMM)
#define NBH        (BS * HEADS)

// ---------------------------------------------------------------------------
// Scratch
// ---------------------------------------------------------------------------
__device__ __half g_xmm_h[M_ROWS * DIM];
__device__ __half g_xmm_l[M_ROWS * DIM];
__device__ __half g_xsrc_h[M_ROWS * DIM];
__device__ __half g_xsrc_l[M_ROWS * DIM];
__device__ __half g_WqT_h[DIM * DIM];
__device__ __half g_WkvT_h[KVDIM * DIM];
__device__ __half g_WpT_h[DIM * DIM];

__device__ __half g_Qh[NBH * NMM * HD];
__device__ __half g_Ql[NBH * NMM * HD];
__device__ __half g_Kh[NBH * NKV * HD];
__device__ __half g_Vh[NBH * NKV * HD];
__device__ __half g_Oh[M_ROWS * DIM];
__device__ float g_attn_fallback[ATTN_ELEMS];

// ---------------------------------------------------------------------------
// PTX helpers
// ---------------------------------------------------------------------------
__device__ __forceinline__ uint32_t smem_u32(const void* p) {
    uint32_t a;
    asm("{ .reg .u64 t; cvta.to.shared.u64 t, %1; cvt.u32.u64 %0, t; }" : "=r"(a) : "l"(p));
    return a;
}
__device__ __forceinline__ void cp_async16(uint32_t sa, const void* gp) {
    asm volatile("cp.async.cg.shared.global [%0], [%1], 16;" :: "r"(sa), "l"(gp) : "memory");
}
__device__ __forceinline__ void cp_commit() {
    asm volatile("cp.async.commit_group;" ::: "memory");
}
template <int N>
__device__ __forceinline__ void cp_wait() {
    asm volatile("cp.async.wait_group %0;" :: "n"(N) : "memory");
}
__device__ __forceinline__ void ldsm4(uint32_t& r0, uint32_t& r1, uint32_t& r2, uint32_t& r3,
                                      uint32_t addr) {
    asm volatile("ldmatrix.sync.aligned.m8n8.x4.shared.b16 {%0,%1,%2,%3}, [%4];"
                 : "=r"(r0), "=r"(r1), "=r"(r2), "=r"(r3) : "r"(addr));
}
__device__ __forceinline__ void ldsm4t(uint32_t& r0, uint32_t& r1, uint32_t& r2, uint32_t& r3,
                                       uint32_t addr) {
    asm volatile("ldmatrix.sync.aligned.m8n8.x4.trans.shared.b16 {%0,%1,%2,%3}, [%4];"
                 : "=r"(r0), "=r"(r1), "=r"(r2), "=r"(r3) : "r"(addr));
}
__device__ __forceinline__ void mma16816(float* c, const uint32_t* a, uint32_t b0, uint32_t b1) {
    asm volatile(
        "mma.sync.aligned.m16n8k16.row.col.f32.f16.f16.f32 "
        "{%0,%1,%2,%3}, {%4,%5,%6,%7}, {%8,%9}, {%0,%1,%2,%3};"
        : "+f"(c[0]), "+f"(c[1]), "+f"(c[2]), "+f"(c[3])
        : "r"(a[0]), "r"(a[1]), "r"(a[2]), "r"(a[3]), "r"(b0), "r"(b1));
}

__device__ __forceinline__ void pack_hl(float f0, float f1, uint32_t& h, uint32_t& l) {
    __half h0 = __float2half_rn(f0);
    __half h1 = __float2half_rn(f1);
    __half l0 = __float2half_rn(f0 - __half2float(h0));
    __half l1 = __float2half_rn(f1 - __half2float(h1));
    __half2 hp = __halves2half2(h0, h1);
    __half2 lp = __halves2half2(l0, l1);
    h = *reinterpret_cast<uint32_t*>(&hp);
    l = *reinterpret_cast<uint32_t*>(&lp);
}
__device__ __forceinline__ uint32_t pack_h(float f0, float f1) {
    __half2 hp = __halves2half2(__float2half_rn(f0), __float2half_rn(f1));
    return *reinterpret_cast<uint32_t*>(&hp);
}

// ---------------------------------------------------------------------------
// Fused input-prep + weight transposes: one launch, disjoint block ranges.
// ---------------------------------------------------------------------------
__device__ __forceinline__ void split4(float4 v, uint2& hv, uint2& lv) {
    uint32_t h0, l0, h1, l1;
    pack_hl(v.x, v.y, h0, l0);
    pack_hl(v.z, v.w, h1, l1);
    hv.x = h0; hv.y = h1; lv.x = l0; lv.y = l1;
}

#define N4 (M_ROWS * DIM / 4)
#define PREP_BLOCKS (2 * N4 / 256)          // 12288
#define TR_BLOCKS   (96 * 24)               // 2304

__global__ __launch_bounds__(256)
void prep_all_kernel(const float4* __restrict__ xmm,
                     const float* __restrict__ xv, const float* __restrict__ xa,
                     uint2* __restrict__ xmm_h, uint2* __restrict__ xmm_l,
                     uint2* __restrict__ xsrc_h, uint2* __restrict__ xsrc_l,
                     const float* __restrict__ Wq, const float* __restrict__ Wkv,
                     const float* __restrict__ Wp,
                     __half* __restrict__ WqT, __half* __restrict__ WkvT,
                     __half* __restrict__ WpT) {
    const int bx = blockIdx.x;
    if (bx < PREP_BLOCKS) {
        int i = bx * 256 + threadIdx.x;
        if (i < N4) {
            uint2 hv, lv;
            split4(xmm[i], hv, lv);
            xmm_h[i] = hv;
            xmm_l[i] = lv;
        } else {
            i -= N4;
            const int C4 = DIM / 4;
            int row = i / C4;
            int c4  = i - row * C4;
            int b = row >> 8;
            int r = row & 255;
            const float4* src = (r < NV)
                ? reinterpret_cast<const float4*>(xv + (size_t)(b * NV + r) * DIM)
                : reinterpret_cast<const float4*>(xa + (size_t)(b * NA + (r - NV)) * DIM);
            uint2 hv, lv;
            split4(src[c4], hv, lv);
            xsrc_h[i] = hv;
            xsrc_l[i] = lv;
        }
    } else {
        __shared__ float t[32][33];
        int b2 = bx - PREP_BLOCKS;
        int nbx = b2 % 96;          // col-block across the 3 matrices
        int ky  = b2 / 96;          // k-block (0..23)
        const float* W; __half* T; int N; int nb;
        if (nbx < 24)      { W = Wq;  T = WqT;  N = DIM;   nb = nbx; }
        else if (nbx < 72) { W = Wkv; T = WkvT; N = KVDIM; nb = nbx - 24; }
        else               { W = Wp;  T = WpT;  N = DIM;   nb = nbx - 72; }
        int k0 = ky * 32, n0 = nb * 32;
        int x = threadIdx.x & 31, y = threadIdx.x >> 5;
        #pragma unroll
        for (int i = 0; i < 32; i += 8)
            t[y + i][x] = W[(size_t)(k0 + y + i) * N + n0 + x];
        __syncthreads();
        #pragma unroll
        for (int i = 0; i < 32; i += 8)
            T[(size_t)(n0 + y + i) * DIM + k0 + x] = __float2half_rn(t[x][y + i]);
    }
}

// ---------------------------------------------------------------------------
// fp16 HMMA GEMM, runtime epilogue select.
// mode 0: out-proj (1-term A, bias, fp32 C). mode 1: merged Q+KV projection
//   (2-term A; blockIdx.x < 6 -> Q epi; else KV epi).
// ---------------------------------------------------------------------------
#define GK 768
#define PAD_ROW 80
#define ARR_BYTES (128 * PAD_ROW)
#define STAGE_BYTES (3 * ARR_BYTES)
#define GEMM_SMEM (3 * STAGE_BYTES)

__global__ __launch_bounds__(256, 2)
void proj_kernel(int mode,
                 const __half* __restrict__ A0h, const __half* __restrict__ A0l,
                 const __half* __restrict__ B0T,
                 const __half* __restrict__ A1h, const __half* __restrict__ A1l,
                 const __half* __restrict__ B1T,
                 const float* __restrict__ bias, float* __restrict__ C,
                 __half* __restrict__ QhO, __half* __restrict__ QlO,
                 __half* __restrict__ KhO, __half* __restrict__ VhO) {
    extern __shared__ char smem[];
    const uint32_t sb = smem_u32(smem);

    const int tid  = threadIdx.x;
    const int lane = tid & 31;
    const int wid  = tid >> 5;
    const int wr   = wid >> 2;
    const int wc   = wid & 3;
    const int m0   = blockIdx.y * 128;
    const int twoTerm = (mode != 0);

    int epi, n0;
    const __half *Ahp, *Alp, *BTp;
    if (mode == 0) {
        epi = 0; Ahp = A0h; Alp = A0l; BTp = B0T; n0 = blockIdx.x * 128;
    } else if (blockIdx.x < 6) {
        epi = 1; Ahp = A0h; Alp = A0l; BTp = B0T; n0 = blockIdx.x * 128;
    } else {
        epi = 2; Ahp = A1h; Alp = A1l; BTp = B1T; n0 = (blockIdx.x - 6) * 128;
    }

    const __half* base0 = Ahp + (size_t)m0 * GK;
    const __half* base1 = Alp + (size_t)m0 * GK;
    const __half* base2 = BTp + (size_t)n0 * GK;

    auto issue_stage = [&](int chunk, int s) {
        const int k0 = chunk << 5;
        const uint32_t sbase = sb + s * STAGE_BYTES;
        #pragma unroll
        for (int it = 0; it < 6; it++) {
            const int arr = it >> 1;
            if (arr == 1 && !twoTerm) continue;
            const int j   = tid + (it & 1) * 256;
            const int row = j >> 2;
            const int q   = j & 3;
            const __half* gp =
                (arr == 0 ? base0 : arr == 1 ? base1 : base2)
                + (size_t)row * GK + k0 + q * 8;
            cp_async16(sbase + arr * ARR_BYTES + row * PAD_ROW + q * 16, gp);
        }
        cp_commit();
    };

    float c[4][4][4];
    #pragma unroll
    for (int i = 0; i < 4; i++)
        #pragma unroll
        for (int j = 0; j < 4; j++)
            #pragma unroll
            for (int k = 0; k < 4; k++) c[i][j][k] = 0.0f;

    const int lr   = lane & 15;
    const int lc16 = (lane >> 4) * 16;

    issue_stage(0, 0);
    issue_stage(1, 1);

    const int nchunks = GK / 32;  // 24
    for (int i = 0; i < nchunks; i++) {
        if (i + 1 < nchunks) cp_wait<1>(); else cp_wait<0>();
        __syncthreads();
        if (i + 2 < nchunks) issue_stage(i + 2, (i + 2) % 3);

        const uint32_t st = sb + (i % 3) * STAGE_BYTES;
        const uint32_t aH_base = st + 0 * ARR_BYTES + (wr * 64 + lr) * PAD_ROW + lc16;
        const uint32_t aL_base = st + 1 * ARR_BYTES + (wr * 64 + lr) * PAD_ROW + lc16;
        const uint32_t bH_base = st + 2 * ARR_BYTES + (wc * 32 + lr) * PAD_ROW + lc16;

        #pragma unroll
        for (int kk = 0; kk < 2; kk++) {
            const uint32_t ko = kk * 32;
            uint32_t bh[4][2];
            #pragma unroll
            for (int bt = 0; bt < 2; bt++) {
                uint32_t r0, r1, r2, r3;
                ldsm4(r0, r1, r2, r3, bH_base + bt * 16 * PAD_ROW + ko);
                bh[bt * 2 + 0][0] = r0; bh[bt * 2 + 0][1] = r2;
                bh[bt * 2 + 1][0] = r1; bh[bt * 2 + 1][1] = r3;
            }
            #pragma unroll
            for (int mt = 0; mt < 4; mt++) {
                uint32_t aH[4], aL[4];
                ldsm4(aH[0], aH[1], aH[2], aH[3], aH_base + mt * 16 * PAD_ROW + ko);
                if (twoTerm)
                    ldsm4(aL[0], aL[1], aL[2], aL[3], aL_base + mt * 16 * PAD_ROW + ko);
                #pragma unroll
                for (int ni = 0; ni < 4; ni++) mma16816(c[mt][ni], aH, bh[ni][0], bh[ni][1]);
                if (twoTerm) {
                    #pragma unroll
                    for (int ni = 0; ni < 4; ni++) mma16816(c[mt][ni], aL, bh[ni][0], bh[ni][1]);
                }
            }
        }
    }

    // Epilogue
    const int crow0 = m0 + wr * 64 + (lane >> 2);
    const int ccol0 = n0 + wc * 32 + (lane & 3) * 2;
    #pragma unroll
    for (int mt = 0; mt < 4; mt++) {
        #pragma unroll
        for (int ni = 0; ni < 4; ni++) {
            const int cc = ccol0 + ni * 8;
            const float* cf = c[mt][ni];
            const int r0 = crow0 + mt * 16;
            const int r1 = r0 + 8;
            if (epi == 0) {
                float b0 = bias[cc], b1 = bias[cc + 1];
                float2 v0 = { cf[0] + b0, cf[1] + b1 };
                float2 v1 = { cf[2] + b0, cf[3] + b1 };
                *reinterpret_cast<float2*>(C + (size_t)r0 * DIM + cc) = v0;
                *reinterpret_cast<float2*>(C + (size_t)r1 * DIM + cc) = v1;
            } else if (epi == 1) {
                const int h = cc >> 6, d = cc & 63;
                #pragma unroll
                for (int s = 0; s < 2; s++) {
                    const int r = s ? r1 : r0;
                    const int b = r >> 8, q = r & 255;
                    size_t idx = (((size_t)(b * HEADS + h)) * NMM + q) * HD + d;
                    uint32_t hh, ll;
                    pack_hl(cf[s * 2], cf[s * 2 + 1], hh, ll);
                    *reinterpret_cast<uint32_t*>(QhO + idx) = hh;
                    *reinterpret_cast<uint32_t*>(QlO + idx) = ll;
                }
            } else {
                const bool isK = (cc < DIM);
                const int ccl = isK ? cc : cc - DIM;
                const int h = ccl >> 6, d = ccl & 63;
                __half* Hd = isK ? KhO : VhO;
                #pragma unroll
                for (int s = 0; s < 2; s++) {
                    const int r = s ? r1 : r0;
                    const int b = r >> 8, t = r & 255;
                    size_t idx = (((size_t)(b * HEADS + h)) * NKV + t) * HD + d;
                    *reinterpret_cast<uint32_t*>(Hd + idx) = pack_h(cf[s * 2], cf[s * 2 + 1]);
                }
            }
        }
    }
}

// ---------------------------------------------------------------------------
// Fused attention: QK + softmax + attn write + AV.
// CTA: 64 q rows, 128 threads (4 warps); each warp owns 16 q rows x ALL 256
// tokens -> warp-local softmax, P stays in registers. 2 CTAs/SM.
// cp.async in two groups: (Q,K) then (V) so QK starts before V lands.
// ---------------------------------------------------------------------------
#define FA_PAD 144
#define FA_QH 0
#define FA_QL (64 * FA_PAD)               // 9216
#define FA_K  (2 * 64 * FA_PAD)           // 18432
#define FA_V  (FA_K + 256 * FA_PAD)       // 55296
#define FA_SMEM (FA_V + 256 * FA_PAD)     // 92160

__global__ __launch_bounds__(128, 2)
void fused_attn_kernel(const __half* __restrict__ Qh, const __half* __restrict__ Ql,
                       const __half* __restrict__ Kh, const __half* __restrict__ Vh,
                       float* __restrict__ attnF, __half* __restrict__ Oh,
                       int writeAttn) {
    extern __shared__ char smem[];
    const uint32_t sb = smem_u32(smem);
    const int bh = blockIdx.y;
    const int q0 = blockIdx.x * 64;
    const int tid  = threadIdx.x;
    const int lane = tid & 31;
    const int wid  = tid >> 5;

    const __half* gQh = Qh + ((size_t)bh * NMM + q0) * HD;
    const __half* gQl = Ql + ((size_t)bh * NMM + q0) * HD;
    const __half* gKh = Kh + (size_t)bh * NKV * HD;
    const __half* gVh = Vh + (size_t)bh * NKV * HD;

    // Group 1: Q + K
    for (int idx = tid; idx < 512; idx += 128) {
        int row = idx >> 3, cq = idx & 7;
        cp_async16(sb + FA_QH + row * FA_PAD + cq * 16, gQh + row * HD + cq * 8);
        cp_async16(sb + FA_QL + row * FA_PAD + cq * 16, gQl + row * HD + cq * 8);
    }
    for (int idx = tid; idx < 2048; idx += 128) {
        int row = idx >> 3, cq = idx & 7;
        cp_async16(sb + FA_K + row * FA_PAD + cq * 16, gKh + row * HD + cq * 8);
    }
    cp_commit();
    // Group 2: V
    for (int idx = tid; idx < 2048; idx += 128) {
        int row = idx >> 3, cq = idx & 7;
        cp_async16(sb + FA_V + row * FA_PAD + cq * 16, gVh + row * HD + cq * 8);
    }
    cp_commit();

    cp_wait<1>();   // Q + K ready
    __syncthreads();

    const int lr = lane & 15;
    const int lc16 = (lane >> 4) * 16;
    const int rowbase = wid * 16;

    // ---- QK: S[16 x 256] ----
    float c[32][4];
    #pragma unroll
    for (int j = 0; j < 32; j++)
        #pragma unroll
        for (int k = 0; k < 4; k++) c[j][k] = 0.0f;

    #pragma unroll
    for (int kk = 0; kk < 4; kk++) {
        const uint32_t ko = kk * 32;
        uint32_t aH[4], aL[4];
        const uint32_t ab = sb + FA_QH + (rowbase + lr) * FA_PAD + ko + lc16;
        ldsm4(aH[0], aH[1], aH[2], aH[3], ab);
        ldsm4(aL[0], aL[1], aL[2], aL[3], ab + FA_QL);
        #pragma unroll
        for (int tb = 0; tb < 16; tb++) {
            const uint32_t bb = sb + FA_K + (tb * 16 + lr) * FA_PAD + ko + lc16;
            uint32_t h0, h1, h2, h3;
            ldsm4(h0, h1, h2, h3, bb);
            mma16816(c[tb * 2],     aH, h0, h2);
            mma16816(c[tb * 2],     aL, h0, h2);
            mma16816(c[tb * 2 + 1], aH, h1, h3);
            mma16816(c[tb * 2 + 1], aL, h1, h3);
        }
    }

    // ---- warp-local softmax over 256 tokens ----
    const float scale = 0.125f;
    #pragma unroll
    for (int s2 = 0; s2 < 2; s2++) {
        float m = -INFINITY;
        #pragma unroll
        for (int nt = 0; nt < 32; nt++) {
            m = fmaxf(m, c[nt][s2 * 2]);
            m = fmaxf(m, c[nt][s2 * 2 + 1]);
        }
        m = fmaxf(m, __shfl_xor_sync(0xffffffffu, m, 1));
        m = fmaxf(m, __shfl_xor_sync(0xffffffffu, m, 2));
        float sum = 0.0f;
        #pragma unroll
        for (int nt = 0; nt < 32; nt++) {
            float e0 = __expf((c[nt][s2 * 2]     - m) * scale);
            float e1 = __expf((c[nt][s2 * 2 + 1] - m) * scale);
            c[nt][s2 * 2]     = e0;
            c[nt][s2 * 2 + 1] = e1;
            sum += e0 + e1;
        }
        sum += __shfl_xor_sync(0xffffffffu, sum, 1);
        sum += __shfl_xor_sync(0xffffffffu, sum, 2);
        float inv = 1.0f / sum;
        #pragma unroll
        for (int nt = 0; nt < 32; nt++) {
            c[nt][s2 * 2]     *= inv;
            c[nt][s2 * 2 + 1] *= inv;
        }
    }

    // ---- write attn (fp32) straight from fragments ----
    if (writeAttn) {
        const int r  = lane >> 2;
        const int c0 = (lane & 3) * 2;
        float* rowp0 = attnF + ((size_t)bh * NMM + q0 + rowbase + r)     * NKV + c0;
        float* rowp1 = attnF + ((size_t)bh * NMM + q0 + rowbase + r + 8) * NKV + c0;
        #pragma unroll
        for (int nt = 0; nt < 32; nt++) {
            float2 v0 = { c[nt][0], c[nt][1] };
            float2 v1 = { c[nt][2], c[nt][3] };
            *reinterpret_cast<float2*>(rowp0 + nt * 8) = v0;
            *reinterpret_cast<float2*>(rowp1 + nt * 8) = v1;
        }
    }

    cp_wait<0>();   // V ready
    __syncthreads();

    // ---- AV: O[16 x 64] = P @ V ----
    float o[8][4];
    #pragma unroll
    for (int j = 0; j < 8; j++)
        #pragma unroll
        for (int k = 0; k < 4; k++) o[j][k] = 0.0f;

    #pragma unroll
    for (int kt = 0; kt < 16; kt++) {
        uint32_t a[4];
        a[0] = pack_h(c[2 * kt][0],     c[2 * kt][1]);
        a[1] = pack_h(c[2 * kt][2],     c[2 * kt][3]);
        a[2] = pack_h(c[2 * kt + 1][0], c[2 * kt + 1][1]);
        a[3] = pack_h(c[2 * kt + 1][2], c[2 * kt + 1][3]);
        #pragma unroll
        for (int dblk = 0; dblk < 4; dblk++) {
            uint32_t v0, v1, v2, v3;
            const uint32_t vb = sb + FA_V + (kt * 16 + lr) * FA_PAD + dblk * 32 + lc16;
            ldsm4t(v0, v1, v2, v3, vb);
            mma16816(o[dblk * 2],     a, v0, v1);
            mma16816(o[dblk * 2 + 1], a, v2, v3);
        }
    }

    // ---- epilogue: O hi (fp16) -> [b*256+q][h*64+d] ----
    const int b = bh / HEADS, h = bh % HEADS;
    const int r = lane >> 2;
    #pragma unroll
    for (int j = 0; j < 8; j++) {
        const int d = j * 8 + (lane & 3) * 2;
        #pragma unroll
        for (int s = 0; s < 2; s++) {
            const int q = q0 + rowbase + r + s * 8;
            size_t idx = ((size_t)(b * NMM + q)) * DIM + h * HD + d;
            *reinterpret_cast<uint32_t*>(Oh + idx) = pack_h(o[j][s * 2], o[j][s * 2 + 1]);
        }
    }
}

// ---------------------------------------------------------------------------
// Launch
// ---------------------------------------------------------------------------
extern "C" void kernel_launch(void* const* d_in, const int* in_sizes, int n_in,
                              void* d_out, int out_size) {
    const float* xmm   = (const float*)d_in[0];
    const float* xv    = (const float*)d_in[1];
    const float* xa    = (const float*)d_in[2];
    const float* Wq    = (const float*)d_in[3];
    const float* Wkv   = (const float*)d_in[4];
    const float* Wproj = (const float*)d_in[5];
    const float* bproj = (const float*)d_in[6];
    float* out = (float*)d_out;

    __half *xmm_h, *xmm_l, *xsrc_h, *xsrc_l;
    __half *WqT_h, *WkvT_h, *WpT_h;
    __half *Qh, *Ql, *Kh, *Vh, *Oh;
    float* attn_fb;
    cudaGetSymbolAddress((void**)&xmm_h,  g_xmm_h);
    cudaGetSymbolAddress((void**)&xmm_l,  g_xmm_l);
    cudaGetSymbolAddress((void**)&xsrc_h, g_xsrc_h);
    cudaGetSymbolAddress((void**)&xsrc_l, g_xsrc_l);
    cudaGetSymbolAddress((void**)&WqT_h,  g_WqT_h);
    cudaGetSymbolAddress((void**)&WkvT_h, g_WkvT_h);
    cudaGetSymbolAddress((void**)&WpT_h,  g_WpT_h);
    cudaGetSymbolAddress((void**)&Qh,  g_Qh);
    cudaGetSymbolAddress((void**)&Ql,  g_Ql);
    cudaGetSymbolAddress((void**)&Kh,  g_Kh);
    cudaGetSymbolAddress((void**)&Vh,  g_Vh);
    cudaGetSymbolAddress((void**)&Oh,  g_Oh);
    cudaGetSymbolAddress((void**)&attn_fb, g_attn_fallback);

    const int writeAttn = (out_size >= (OUT_ELEMS + ATTN_ELEMS)) ? 1 : 0;
    float* attn = writeAttn ? (out + OUT_ELEMS) : attn_fb;

    cudaFuncSetAttribute(proj_kernel, cudaFuncAttributeMaxDynamicSharedMemorySize, GEMM_SMEM);
    cudaFuncSetAttribute(fused_attn_kernel, cudaFuncAttributeMaxDynamicSharedMemorySize, FA_SMEM);

    // 1) input splits + weight transposes, one launch
    prep_all_kernel<<<PREP_BLOCKS + TR_BLOCKS, 256>>>(
        (const float4*)xmm, xv, xa,
        (uint2*)xmm_h, (uint2*)xmm_l, (uint2*)xsrc_h, (uint2*)xsrc_l,
        Wq, Wkv, Wproj, WqT_h, WkvT_h, WpT_h);

    // 2) merged Q + KV projections
    proj_kernel<<<dim3(18, M_ROWS / 128), 256, GEMM_SMEM>>>(
        1, xmm_h, xmm_l, WqT_h, xsrc_h, xsrc_l, WkvT_h,
        nullptr, nullptr, Qh, Ql, Kh, Vh);

    // 3) fused QK + softmax + attn write + AV (64-row CTAs, 2/SM)
    fused_attn_kernel<<<dim3(NMM / 64, NBH), 128, FA_SMEM>>>(
        Qh, Ql, Kh, Vh, attn, Oh, writeAttn);

    // 4) out-proj (1-term A)
    proj_kernel<<<dim3(6, M_ROWS / 128), 256, GEMM_SMEM>>>(
        0, Oh, Oh, WpT_h, nullptr, nullptr, nullptr,
        bproj, out, nullptr, nullptr, nullptr, nullptr);
}